// round 2
// baseline (speedup 1.0000x reference)
#include <cuda_runtime.h>
#include <cuda_bf16.h>
#include <math_constants.h>

// Problem constants
#define BATCH   2
#define SEQ     2048
#define HIDDEN  1024
#define HEADS   16
#define HEAD_D  64
#define QKV_N   (3 * HIDDEN)          // 3072
#define M_TOT   (BATCH * SEQ)         // 4096
#define ATTN_SCALE 125.0f             // TEMP_K / sqrt(HEAD_D) = 1000/8

// Scratch (allocation-free rule: __device__ globals)
__device__ float g_qkv[M_TOT * QKV_N];   // 48 MB
__device__ float g_ctx[M_TOT * HIDDEN];  // 16 MB

// ---------------------------------------------------------------------------
// FMA-pipe exp: exp(x) for x <= 0 (underflows to ~0 for very negative x).
// Range-reduce base-2 with rintf (|f|<=0.5), degree-5 Horner for e^(f*ln2),
// exponent via bit splice. Rel err ~2.5e-6. No MUFU.
// ---------------------------------------------------------------------------
__device__ __forceinline__ float fast_exp(float x)
{
    float t  = x * 1.4426950408889634f;     // x * log2(e)
    t        = fmaxf(t, -126.0f);           // clamp (handles -inf, overflow)
    float fi = rintf(t);
    float f  = (t - fi) * 0.6931471805599453f;   // back to natural, |f|<=0.347
    float p  = 8.3333333e-3f;                    // 1/120
    p = fmaf(p, f, 4.1666668e-2f);               // 1/24
    p = fmaf(p, f, 1.6666667e-1f);               // 1/6
    p = fmaf(p, f, 5.0e-1f);
    p = fmaf(p, f, 1.0f);
    p = fmaf(p, f, 1.0f);
    int ei = (int)fi;                            // in [-126, 0]
    float sc = __int_as_float((ei + 127) << 23); // 2^fi
    return p * sc;
}

// ---------------------------------------------------------------------------
// Tiled fp32 GEMM with bias: C[M,N] = A[M,K] @ B[K,N] + bias[N]
// BM=BN=128, BK=16, 256 threads, 8x8 micro-tile, double-buffered smem with
// register prefetch (global load latency hidden behind compute).
// ---------------------------------------------------------------------------
__global__ __launch_bounds__(256, 2)
void sgemm_bias(const float* __restrict__ A, const float* __restrict__ B,
                const float* __restrict__ bias, float* __restrict__ C,
                int M, int N, int K)
{
    const int BM = 128, BN = 128, BK = 16;
    __shared__ float As[2][BK][BM];   // transposed A tile
    __shared__ float Bs[2][BK][BN];

    int tid = threadIdx.x;
    int bx = blockIdx.x;              // N tile
    int by = blockIdx.y;              // M tile
    int ty = tid >> 4;                // 0..15 (row group)
    int tx = tid & 15;                // 0..15 (col group)

    // A-tile: 128 rows x 16 cols = 512 float4; 2 per thread
    int arow = tid >> 1;              // 0..127
    int acol = (tid & 1) * 8;         // 0 or 8
    // B-tile: 16 rows x 128 cols = 512 float4; 2 per thread
    int brow = tid >> 4;              // 0..15
    int bcol = (tid & 15) * 8;        // 0..120

    const float* Aptr = A + (size_t)(by * BM + arow) * K + acol;
    const float* Bptr = B + (size_t)brow * N + bx * BN + bcol;

    float acc[8][8];
    #pragma unroll
    for (int i = 0; i < 8; i++)
        #pragma unroll
        for (int j = 0; j < 8; j++) acc[i][j] = 0.0f;

    const int ntiles = K / BK;

    // preload tile 0
    float4 pa0 = *(const float4*)(Aptr + 0);
    float4 pa1 = *(const float4*)(Aptr + 4);
    float4 pb0 = *(const float4*)(Bptr + 0);
    float4 pb1 = *(const float4*)(Bptr + 4);
    As[0][acol + 0][arow] = pa0.x; As[0][acol + 1][arow] = pa0.y;
    As[0][acol + 2][arow] = pa0.z; As[0][acol + 3][arow] = pa0.w;
    As[0][acol + 4][arow] = pa1.x; As[0][acol + 5][arow] = pa1.y;
    As[0][acol + 6][arow] = pa1.z; As[0][acol + 7][arow] = pa1.w;
    *(float4*)&Bs[0][brow][bcol + 0] = pb0;
    *(float4*)&Bs[0][brow][bcol + 4] = pb1;
    __syncthreads();

    for (int kt = 0; kt < ntiles; kt++) {
        int cur = kt & 1, nxt = cur ^ 1;
        if (kt + 1 < ntiles) {
            int k0 = (kt + 1) * BK;
            pa0 = *(const float4*)(Aptr + k0);
            pa1 = *(const float4*)(Aptr + k0 + 4);
            pb0 = *(const float4*)(Bptr + (size_t)k0 * N);
            pb1 = *(const float4*)(Bptr + (size_t)k0 * N + 4);
        }

        #pragma unroll
        for (int k = 0; k < BK; k++) {
            float4 a0 = *(const float4*)&As[cur][k][ty * 8];
            float4 a1 = *(const float4*)&As[cur][k][ty * 8 + 4];
            float4 b0 = *(const float4*)&Bs[cur][k][tx * 4];
            float4 b1 = *(const float4*)&Bs[cur][k][64 + tx * 4];
            float ra[8] = {a0.x, a0.y, a0.z, a0.w, a1.x, a1.y, a1.z, a1.w};
            float rb[8] = {b0.x, b0.y, b0.z, b0.w, b1.x, b1.y, b1.z, b1.w};
            #pragma unroll
            for (int i = 0; i < 8; i++)
                #pragma unroll
                for (int j = 0; j < 8; j++)
                    acc[i][j] = fmaf(ra[i], rb[j], acc[i][j]);
        }

        if (kt + 1 < ntiles) {
            As[nxt][acol + 0][arow] = pa0.x; As[nxt][acol + 1][arow] = pa0.y;
            As[nxt][acol + 2][arow] = pa0.z; As[nxt][acol + 3][arow] = pa0.w;
            As[nxt][acol + 4][arow] = pa1.x; As[nxt][acol + 5][arow] = pa1.y;
            As[nxt][acol + 6][arow] = pa1.z; As[nxt][acol + 7][arow] = pa1.w;
            *(float4*)&Bs[nxt][brow][bcol + 0] = pb0;
            *(float4*)&Bs[nxt][brow][bcol + 4] = pb1;
        }
        __syncthreads();
    }

    // Epilogue: columns are split (tx*4) and (64 + tx*4)
    int c0 = bx * BN + tx * 4;
    int c1 = bx * BN + 64 + tx * 4;
    float4 bb0 = *(const float4*)(bias + c0);
    float4 bb1 = *(const float4*)(bias + c1);
    #pragma unroll
    for (int i = 0; i < 8; i++) {
        int row = by * BM + ty * 8 + i;
        float4 o0, o1;
        o0.x = acc[i][0] + bb0.x; o0.y = acc[i][1] + bb0.y;
        o0.z = acc[i][2] + bb0.z; o0.w = acc[i][3] + bb0.w;
        o1.x = acc[i][4] + bb1.x; o1.y = acc[i][5] + bb1.y;
        o1.z = acc[i][6] + bb1.z; o1.w = acc[i][7] + bb1.w;
        *(float4*)(C + (size_t)row * N + c0) = o0;
        *(float4*)(C + (size_t)row * N + c1) = o1;
    }
}

// ---------------------------------------------------------------------------
// Causal flash attention v2.
// grid = (SEQ/64, HEADS, BATCH), block = 128 threads.
// Two threads per query row (each owns 32 of the 64 head dims).
// Per 64x64 K/V tile: phase 1 computes all 64 scores (pair-combined via
// shfl_xor) and tile max; single accumulator rescale; phase 2 does
// exp (FMA-pipe fast_exp) + PV accumulation. Scores staged in sp[j][row].
// ---------------------------------------------------------------------------
__global__ __launch_bounds__(128)
void attn_kernel(const float* __restrict__ qkv, float* __restrict__ ctx)
{
    __shared__ float ks[64][64];
    __shared__ float vs[64][64];
    __shared__ float sp[64][64];   // [key j][query row]

    int qt = (int)gridDim.x - 1 - (int)blockIdx.x;   // heavy tiles first
    int h  = blockIdx.y;
    int b  = blockIdx.z;
    int t  = threadIdx.x;
    int row  = t >> 1;            // 0..63 (query row within tile)
    int half = t & 1;             // which 32-dim half
    int hoff = half * 32;

    int srow = qt * 64 + row;
    const float* qrow = qkv + (size_t)(b * SEQ + srow) * QKV_N + h * HEAD_D + hoff;

    float q[32];
    #pragma unroll
    for (int d = 0; d < 32; d += 4) {
        float4 v4 = *(const float4*)(qrow + d);
        q[d + 0] = v4.x * ATTN_SCALE;
        q[d + 1] = v4.y * ATTN_SCALE;
        q[d + 2] = v4.z * ATTN_SCALE;
        q[d + 3] = v4.w * ATTN_SCALE;
    }

    float acc[32];
    #pragma unroll
    for (int d = 0; d < 32; d++) acc[d] = 0.0f;
    float m = -CUDART_INF_F;
    float l = 0.0f;

    for (int kt = 0; kt <= qt; kt++) {
        __syncthreads();   // protect previous tile before overwrite
        const float* kr = qkv + (size_t)(b * SEQ + kt * 64 + row) * QKV_N
                        + HIDDEN + h * HEAD_D + hoff;
        const float* vr = kr + HIDDEN;
        #pragma unroll
        for (int i = 0; i < 8; i++) {
            *(float4*)&ks[row][hoff + 4 * i] = *(const float4*)(kr + 4 * i);
            *(float4*)&vs[row][hoff + 4 * i] = *(const float4*)(vr + 4 * i);
        }
        __syncthreads();

        bool diag = (kt == qt);
        float tmax = -CUDART_INF_F;

        // Phase 1: scores + tile max
        #pragma unroll 4
        for (int j = 0; j < 64; j++) {
            float part = 0.0f;
            #pragma unroll
            for (int d = 0; d < 32; d += 4) {
                float4 k4 = *(const float4*)&ks[j][hoff + d];
                part = fmaf(q[d + 0], k4.x, part);
                part = fmaf(q[d + 1], k4.y, part);
                part = fmaf(q[d + 2], k4.z, part);
                part = fmaf(q[d + 3], k4.w, part);
            }
            float s = part + __shfl_xor_sync(0xffffffffu, part, 1);
            if (diag && j > row) s = -3.0e38f;   // causal mask (exp -> 0)
            if (half == 0) sp[j][row] = s;
            tmax = fmaxf(tmax, s);
        }
        __syncwarp();   // sp written by even lane, read by both lanes (same warp)

        // Single rescale per tile
        float mn   = fmaxf(m, tmax);
        float corr = fast_exp(m - mn);   // 0 on first tile (m = -inf)
        l *= corr;
        #pragma unroll
        for (int d = 0; d < 32; d++) acc[d] *= corr;
        m = mn;

        // Phase 2: exp + PV
        #pragma unroll 2
        for (int j = 0; j < 64; j++) {
            float p = fast_exp(sp[j][row] - mn);
            l += p;
            #pragma unroll
            for (int d = 0; d < 32; d += 4) {
                float4 v4 = *(const float4*)&vs[j][hoff + d];
                acc[d + 0] = fmaf(p, v4.x, acc[d + 0]);
                acc[d + 1] = fmaf(p, v4.y, acc[d + 1]);
                acc[d + 2] = fmaf(p, v4.z, acc[d + 2]);
                acc[d + 3] = fmaf(p, v4.w, acc[d + 3]);
            }
        }
    }

    float inv = 1.0f / l;
    float* out = ctx + (size_t)(b * SEQ + srow) * HIDDEN + h * HEAD_D + hoff;
    #pragma unroll
    for (int d = 0; d < 32; d += 4) {
        float4 o;
        o.x = acc[d + 0] * inv;
        o.y = acc[d + 1] * inv;
        o.z = acc[d + 2] * inv;
        o.w = acc[d + 3] * inv;
        *(float4*)(out + d) = o;
    }
}

// ---------------------------------------------------------------------------
extern "C" void kernel_launch(void* const* d_in, const int* in_sizes, int n_in,
                              void* d_out, int out_size)
{
    const float* x     = (const float*)d_in[0];
    const float* W_qkv = (const float*)d_in[1];
    const float* b_qkv = (const float*)d_in[2];
    const float* W_out = (const float*)d_in[3];
    const float* b_out = (const float*)d_in[4];
    float* out = (float*)d_out;

    float* qkv; float* ctx;
    cudaGetSymbolAddress((void**)&qkv, g_qkv);
    cudaGetSymbolAddress((void**)&ctx, g_ctx);

    // 1) QKV projection: [4096,1024] @ [1024,3072] + bias
    {
        dim3 grid(QKV_N / 128, M_TOT / 128);
        sgemm_bias<<<grid, 256>>>(x, W_qkv, b_qkv, qkv, M_TOT, QKV_N, HIDDEN);
    }
    // 2) Causal attention
    {
        dim3 grid(SEQ / 64, HEADS, BATCH);
        attn_kernel<<<grid, 128>>>(qkv, ctx);
    }
    // 3) Output projection: [4096,1024] @ [1024,1024] + bias
    {
        dim3 grid(HIDDEN / 128, M_TOT / 128);
        sgemm_bias<<<grid, 256>>>(ctx, W_out, b_out, out, M_TOT, HIDDEN, HIDDEN);
    }
}

// round 3
// speedup vs baseline: 1.8338x; 1.8338x over previous
#include <cuda_runtime.h>
#include <cuda_bf16.h>
#include <math_constants.h>

// Problem constants
#define BATCH   2
#define SEQ     2048
#define HIDDEN  1024
#define HEADS   16
#define HEAD_D  64
#define QKV_N   (3 * HIDDEN)          // 3072
#define M_TOT   (BATCH * SEQ)         // 4096
#define ATTN_SCALE 125.0f             // TEMP_K / sqrt(HEAD_D) = 1000/8

// Scratch (allocation-free rule: __device__ globals)
__device__ float g_qkv[M_TOT * QKV_N];   // 48 MB
__device__ float g_ctx[M_TOT * HIDDEN];  // 16 MB

// ---------------------------------------------------------------------------
// Tiled fp32 GEMM with bias: C[M,N] = A[M,K] @ B[K,N] + bias[N]
// BM=BN=128, BK=16, 256 threads, 8x8 micro-tile, double-buffered smem with
// register prefetch. (Unchanged from round 2: measured 598us on QKV.)
// ---------------------------------------------------------------------------
__global__ __launch_bounds__(256, 2)
void sgemm_bias(const float* __restrict__ A, const float* __restrict__ B,
                const float* __restrict__ bias, float* __restrict__ C,
                int M, int N, int K)
{
    const int BM = 128, BN = 128, BK = 16;
    __shared__ float As[2][BK][BM];   // transposed A tile
    __shared__ float Bs[2][BK][BN];

    int tid = threadIdx.x;
    int bx = blockIdx.x;              // N tile
    int by = blockIdx.y;              // M tile
    int ty = tid >> 4;                // 0..15 (row group)
    int tx = tid & 15;                // 0..15 (col group)

    int arow = tid >> 1;              // 0..127
    int acol = (tid & 1) * 8;         // 0 or 8
    int brow = tid >> 4;              // 0..15
    int bcol = (tid & 15) * 8;        // 0..120

    const float* Aptr = A + (size_t)(by * BM + arow) * K + acol;
    const float* Bptr = B + (size_t)brow * N + bx * BN + bcol;

    float acc[8][8];
    #pragma unroll
    for (int i = 0; i < 8; i++)
        #pragma unroll
        for (int j = 0; j < 8; j++) acc[i][j] = 0.0f;

    const int ntiles = K / BK;

    float4 pa0 = *(const float4*)(Aptr + 0);
    float4 pa1 = *(const float4*)(Aptr + 4);
    float4 pb0 = *(const float4*)(Bptr + 0);
    float4 pb1 = *(const float4*)(Bptr + 4);
    As[0][acol + 0][arow] = pa0.x; As[0][acol + 1][arow] = pa0.y;
    As[0][acol + 2][arow] = pa0.z; As[0][acol + 3][arow] = pa0.w;
    As[0][acol + 4][arow] = pa1.x; As[0][acol + 5][arow] = pa1.y;
    As[0][acol + 6][arow] = pa1.z; As[0][acol + 7][arow] = pa1.w;
    *(float4*)&Bs[0][brow][bcol + 0] = pb0;
    *(float4*)&Bs[0][brow][bcol + 4] = pb1;
    __syncthreads();

    for (int kt = 0; kt < ntiles; kt++) {
        int cur = kt & 1, nxt = cur ^ 1;
        if (kt + 1 < ntiles) {
            int k0 = (kt + 1) * BK;
            pa0 = *(const float4*)(Aptr + k0);
            pa1 = *(const float4*)(Aptr + k0 + 4);
            pb0 = *(const float4*)(Bptr + (size_t)k0 * N);
            pb1 = *(const float4*)(Bptr + (size_t)k0 * N + 4);
        }

        #pragma unroll
        for (int k = 0; k < BK; k++) {
            float4 a0 = *(const float4*)&As[cur][k][ty * 8];
            float4 a1 = *(const float4*)&As[cur][k][ty * 8 + 4];
            float4 b0 = *(const float4*)&Bs[cur][k][tx * 4];
            float4 b1 = *(const float4*)&Bs[cur][k][64 + tx * 4];
            float ra[8] = {a0.x, a0.y, a0.z, a0.w, a1.x, a1.y, a1.z, a1.w};
            float rb[8] = {b0.x, b0.y, b0.z, b0.w, b1.x, b1.y, b1.z, b1.w};
            #pragma unroll
            for (int i = 0; i < 8; i++)
                #pragma unroll
                for (int j = 0; j < 8; j++)
                    acc[i][j] = fmaf(ra[i], rb[j], acc[i][j]);
        }

        if (kt + 1 < ntiles) {
            As[nxt][acol + 0][arow] = pa0.x; As[nxt][acol + 1][arow] = pa0.y;
            As[nxt][acol + 2][arow] = pa0.z; As[nxt][acol + 3][arow] = pa0.w;
            As[nxt][acol + 4][arow] = pa1.x; As[nxt][acol + 5][arow] = pa1.y;
            As[nxt][acol + 6][arow] = pa1.z; As[nxt][acol + 7][arow] = pa1.w;
            *(float4*)&Bs[nxt][brow][bcol + 0] = pb0;
            *(float4*)&Bs[nxt][brow][bcol + 4] = pb1;
        }
        __syncthreads();
    }

    int c0 = bx * BN + tx * 4;
    int c1 = bx * BN + 64 + tx * 4;
    float4 bb0 = *(const float4*)(bias + c0);
    float4 bb1 = *(const float4*)(bias + c1);
    #pragma unroll
    for (int i = 0; i < 8; i++) {
        int row = by * BM + ty * 8 + i;
        float4 o0, o1;
        o0.x = acc[i][0] + bb0.x; o0.y = acc[i][1] + bb0.y;
        o0.z = acc[i][2] + bb0.z; o0.w = acc[i][3] + bb0.w;
        o1.x = acc[i][4] + bb1.x; o1.y = acc[i][5] + bb1.y;
        o1.z = acc[i][6] + bb1.z; o1.w = acc[i][7] + bb1.w;
        *(float4*)(C + (size_t)row * N + c0) = o0;
        *(float4*)(C + (size_t)row * N + c1) = o1;
    }
}

// ---------------------------------------------------------------------------
// Causal flash attention v3: outer-product register blocking.
// grid = (SEQ/64, HEADS, BATCH), block = 128 threads, 48KB static smem.
// Thread (ty,tx) ty=t>>4, tx=t&15 owns an 8x4 micro-tile:
//   rows ty*8..ty*8+7, keys tx*4..tx*4+3.
// Per tile: S = Q.K^T GEMM (qs,ks d-major), online softmax (row max via
// 16-lane shfl reduce), P staged into the ks region (aliased), O += P.V GEMM.
// Per k-step: 3 LDS.128 feed 32 FMA -> FMA-bound, not smem-bound.
// ---------------------------------------------------------------------------
__global__ __launch_bounds__(128, 4)
void attn_kernel(const float* __restrict__ qkv, float* __restrict__ ctx)
{
    __shared__ float qs[64 * 64];    // d-major: qs[d*64 + row]
    __shared__ float kps[64 * 64];   // d-major ks[d*64+key]; reused as ps[row*64+key]
    __shared__ float vsm[64 * 64];   // key-major: vsm[key*64 + d]

    int qt = (int)gridDim.x - 1 - (int)blockIdx.x;   // heavy tiles first
    int h  = blockIdx.y;
    int b  = blockIdx.z;
    int t  = threadIdx.x;
    int ty = t >> 4;                 // 0..7  (rows ty*8..+7)
    int tx = t & 15;                 // 0..15 (keys tx*4..+3)

    // ---- load Q tile, transpose to d-major, pre-scale by 125 ----
    {
        int row = t >> 1;            // 0..63
        int dh  = (t & 1) * 32;      // 0 or 32
        const float* qr = qkv + (size_t)(b * SEQ + qt * 64 + row) * QKV_N
                        + h * HEAD_D + dh;
        #pragma unroll
        for (int i = 0; i < 8; i++) {
            float4 v = *(const float4*)(qr + 4 * i);
            int d = dh + 4 * i;
            qs[(d + 0) * 64 + row] = v.x * ATTN_SCALE;
            qs[(d + 1) * 64 + row] = v.y * ATTN_SCALE;
            qs[(d + 2) * 64 + row] = v.z * ATTN_SCALE;
            qs[(d + 3) * 64 + row] = v.w * ATTN_SCALE;
        }
    }

    float o[8][4];
    float m[8], l[8];
    #pragma unroll
    for (int i = 0; i < 8; i++) {
        m[i] = -CUDART_INF_F;
        l[i] = 0.0f;
        #pragma unroll
        for (int j = 0; j < 4; j++) o[i][j] = 0.0f;
    }

    for (int kt = 0; kt <= qt; kt++) {
        __syncthreads();   // (A) previous PV finished reading kps/vsm

        // ---- K tile -> kps d-major (transpose store, 2-way conflict) ----
        {
            int key = t >> 1;
            int dh  = (t & 1) * 32;
            const float* kr = qkv + (size_t)(b * SEQ + kt * 64 + key) * QKV_N
                            + HIDDEN + h * HEAD_D + dh;
            #pragma unroll
            for (int i = 0; i < 8; i++) {
                float4 v = *(const float4*)(kr + 4 * i);
                int d = dh + 4 * i;
                kps[(d + 0) * 64 + key] = v.x;
                kps[(d + 1) * 64 + key] = v.y;
                kps[(d + 2) * 64 + key] = v.z;
                kps[(d + 3) * 64 + key] = v.w;
            }
        }
        // ---- V tile -> vsm key-major (chunk-linear, conflict-free) ----
        {
            #pragma unroll
            for (int i = 0; i < 8; i++) {
                int c = t + 128 * i;
                int key = c >> 4;
                int d0  = (c & 15) * 4;
                const float* vr = qkv + (size_t)(b * SEQ + kt * 64 + key) * QKV_N
                                + 2 * HIDDEN + h * HEAD_D + d0;
                *(float4*)&vsm[key * 64 + d0] = *(const float4*)vr;
            }
        }
        __syncthreads();   // (B) tiles ready

        // ---- score GEMM: s[i][j] = sum_d q[row_i][d] * k[key_j][d] ----
        float s[8][4];
        #pragma unroll
        for (int i = 0; i < 8; i++)
            #pragma unroll
            for (int j = 0; j < 4; j++) s[i][j] = 0.0f;

        #pragma unroll 4
        for (int d = 0; d < 64; d++) {
            float4 b4 = *(const float4*)&kps[d * 64 + tx * 4];
            float4 a0 = *(const float4*)&qs[d * 64 + ty * 8];
            float4 a1 = *(const float4*)&qs[d * 64 + ty * 8 + 4];
            float av[8] = {a0.x, a0.y, a0.z, a0.w, a1.x, a1.y, a1.z, a1.w};
            float bv[4] = {b4.x, b4.y, b4.z, b4.w};
            #pragma unroll
            for (int i = 0; i < 8; i++)
                #pragma unroll
                for (int j = 0; j < 4; j++)
                    s[i][j] = fmaf(av[i], bv[j], s[i][j]);
        }

        // ---- causal mask on the diagonal tile ----
        if (kt == qt) {
            #pragma unroll
            for (int i = 0; i < 8; i++)
                #pragma unroll
                for (int j = 0; j < 4; j++)
                    if (tx * 4 + j > ty * 8 + i) s[i][j] = -CUDART_INF_F;
        }

        // ---- online softmax update (row max across 16 tx lanes) ----
        #pragma unroll
        for (int i = 0; i < 8; i++) {
            float tm = fmaxf(fmaxf(s[i][0], s[i][1]), fmaxf(s[i][2], s[i][3]));
            tm = fmaxf(tm, __shfl_xor_sync(0xffffffffu, tm, 1));
            tm = fmaxf(tm, __shfl_xor_sync(0xffffffffu, tm, 2));
            tm = fmaxf(tm, __shfl_xor_sync(0xffffffffu, tm, 4));
            tm = fmaxf(tm, __shfl_xor_sync(0xffffffffu, tm, 8));
            float mn   = fmaxf(m[i], tm);
            float corr = __expf(m[i] - mn);   // 0 on first tile (m=-inf)
            m[i] = mn;
            float rs = 0.0f;
            #pragma unroll
            for (int j = 0; j < 4; j++) {
                float p = __expf(s[i][j] - mn);   // masked -> exp(-inf)=0
                s[i][j] = p;
                rs += p;
            }
            l[i] = l[i] * corr + rs;
            #pragma unroll
            for (int j = 0; j < 4; j++) o[i][j] *= corr;
        }

        __syncthreads();   // (C) everyone done reading kps as K

        // ---- stage P into kps as ps[row*64 + key] (conflict-free f4 stores) ----
        #pragma unroll
        for (int i = 0; i < 8; i++) {
            float4 pv = make_float4(s[i][0], s[i][1], s[i][2], s[i][3]);
            *(float4*)&kps[(ty * 8 + i) * 64 + tx * 4] = pv;
        }
        __syncthreads();   // (D) P ready

        // ---- PV GEMM: o[i][j] += sum_key p[row_i][key] * v[key][d_j] ----
        #pragma unroll 2
        for (int k = 0; k < 64; k++) {
            float4 b4 = *(const float4*)&vsm[k * 64 + tx * 4];
            float av[8];
            #pragma unroll
            for (int i = 0; i < 8; i++)
                av[i] = kps[(ty * 8 + i) * 64 + k];
            #pragma unroll
            for (int i = 0; i < 8; i++) {
                o[i][0] = fmaf(av[i], b4.x, o[i][0]);
                o[i][1] = fmaf(av[i], b4.y, o[i][1]);
                o[i][2] = fmaf(av[i], b4.z, o[i][2]);
                o[i][3] = fmaf(av[i], b4.w, o[i][3]);
            }
        }
    }

    // ---- finalize: reduce l across tx lanes, normalize, store ----
    #pragma unroll
    for (int i = 0; i < 8; i++) {
        float li = l[i];
        li += __shfl_xor_sync(0xffffffffu, li, 1);
        li += __shfl_xor_sync(0xffffffffu, li, 2);
        li += __shfl_xor_sync(0xffffffffu, li, 4);
        li += __shfl_xor_sync(0xffffffffu, li, 8);
        float inv = 1.0f / li;
        int row = qt * 64 + ty * 8 + i;
        float4 ov;
        ov.x = o[i][0] * inv;
        ov.y = o[i][1] * inv;
        ov.z = o[i][2] * inv;
        ov.w = o[i][3] * inv;
        *(float4*)(ctx + (size_t)(b * SEQ + row) * HIDDEN + h * HEAD_D + tx * 4) = ov;
    }
}

// ---------------------------------------------------------------------------
extern "C" void kernel_launch(void* const* d_in, const int* in_sizes, int n_in,
                              void* d_out, int out_size)
{
    const float* x     = (const float*)d_in[0];
    const float* W_qkv = (const float*)d_in[1];
    const float* b_qkv = (const float*)d_in[2];
    const float* W_out = (const float*)d_in[3];
    const float* b_out = (const float*)d_in[4];
    float* out = (float*)d_out;

    float* qkv; float* ctx;
    cudaGetSymbolAddress((void**)&qkv, g_qkv);
    cudaGetSymbolAddress((void**)&ctx, g_ctx);

    // 1) QKV projection: [4096,1024] @ [1024,3072] + bias
    {
        dim3 grid(QKV_N / 128, M_TOT / 128);
        sgemm_bias<<<grid, 256>>>(x, W_qkv, b_qkv, qkv, M_TOT, QKV_N, HIDDEN);
    }
    // 2) Causal attention
    {
        dim3 grid(SEQ / 64, HEADS, BATCH);
        attn_kernel<<<grid, 128>>>(qkv, ctx);
    }
    // 3) Output projection: [4096,1024] @ [1024,1024] + bias
    {
        dim3 grid(HIDDEN / 128, M_TOT / 128);
        sgemm_bias<<<grid, 256>>>(ctx, W_out, b_out, out, M_TOT, HIDDEN, HIDDEN);
    }
}

// round 7
// speedup vs baseline: 2.5054x; 1.3662x over previous
#include <cuda_runtime.h>
#include <cuda_bf16.h>
#include <math_constants.h>
#include <cstdint>

// Problem constants
#define BATCH   2
#define SEQ     2048
#define HIDDEN  1024
#define HEADS   16
#define HEAD_D  64
#define QKV_N   (3 * HIDDEN)          // 3072
#define M_TOT   (BATCH * SEQ)         // 4096
#define KDIM    1024
#define ATTN_SCALE 125.0f             // TEMP_K / sqrt(HEAD_D)

// ---------------------------------------------------------------------------
// Scratch (__device__ globals per allocation-free rule)
// ---------------------------------------------------------------------------
__device__ float g_qkv[M_TOT * QKV_N];
__device__ float g_ctx[M_TOT * HIDDEN];
__device__ __nv_bfloat16 g_x_hi[M_TOT * HIDDEN];
__device__ __nv_bfloat16 g_x_mid[M_TOT * HIDDEN];
__device__ __nv_bfloat16 g_c_hi[M_TOT * HIDDEN];
__device__ __nv_bfloat16 g_c_mid[M_TOT * HIDDEN];
__device__ __nv_bfloat16 g_wq_hi[QKV_N * KDIM];    // W_qkv^T [3072][1024]
__device__ __nv_bfloat16 g_wq_mid[QKV_N * KDIM];
__device__ __nv_bfloat16 g_wo_hi[HIDDEN * KDIM];   // W_out^T [1024][1024]
__device__ __nv_bfloat16 g_wo_mid[HIDDEN * KDIM];

// ---------------------------------------------------------------------------
__device__ __forceinline__ uint32_t smem_u32(const void* p) {
    uint32_t a;
    asm("{ .reg .u64 t; cvta.to.shared.u64 t, %1; cvt.u32.u64 %0, t; }"
        : "=r"(a) : "l"(p));
    return a;
}

__device__ __forceinline__ void cp16(uint32_t dst, const void* src) {
    asm volatile("cp.async.cg.shared.global [%0], [%1], 16;"
                 :: "r"(dst), "l"(src) : "memory");
}
#define CP_COMMIT() asm volatile("cp.async.commit_group;" ::: "memory")
#define CP_WAIT(n)  asm volatile("cp.async.wait_group %0;" :: "n"(n) : "memory")

__device__ __forceinline__ void ldsm4(uint32_t* r, uint32_t addr) {
    asm volatile("ldmatrix.sync.aligned.m8n8.x4.shared.b16 {%0,%1,%2,%3}, [%4];"
                 : "=r"(r[0]), "=r"(r[1]), "=r"(r[2]), "=r"(r[3]) : "r"(addr));
}

__device__ __forceinline__ void mma16816(float* c, const uint32_t* a,
                                         const uint32_t* b) {
    asm volatile(
        "mma.sync.aligned.m16n8k16.row.col.f32.bf16.bf16.f32 "
        "{%0,%1,%2,%3}, {%4,%5,%6,%7}, {%8,%9}, {%0,%1,%2,%3};"
        : "+f"(c[0]), "+f"(c[1]), "+f"(c[2]), "+f"(c[3])
        : "r"(a[0]), "r"(a[1]), "r"(a[2]), "r"(a[3]), "r"(b[0]), "r"(b[1]));
}

// ---------------------------------------------------------------------------
// Prepass 1: elementwise fp32 -> bf16 (hi, mid) split.  mid = rn(x - hi).
// ---------------------------------------------------------------------------
__global__ __launch_bounds__(256)
void split_rows(const float4* __restrict__ src,
                __nv_bfloat162* __restrict__ hi,
                __nv_bfloat162* __restrict__ mid, int n4)
{
    int i = blockIdx.x * blockDim.x + threadIdx.x;
    if (i >= n4) return;
    float4 v = src[i];
    __nv_bfloat16 h0 = __float2bfloat16_rn(v.x);
    __nv_bfloat16 h1 = __float2bfloat16_rn(v.y);
    __nv_bfloat16 h2 = __float2bfloat16_rn(v.z);
    __nv_bfloat16 h3 = __float2bfloat16_rn(v.w);
    __nv_bfloat16 m0 = __float2bfloat16_rn(v.x - __bfloat162float(h0));
    __nv_bfloat16 m1 = __float2bfloat16_rn(v.y - __bfloat162float(h1));
    __nv_bfloat16 m2 = __float2bfloat16_rn(v.z - __bfloat162float(h2));
    __nv_bfloat16 m3 = __float2bfloat16_rn(v.w - __bfloat162float(h3));
    __nv_bfloat162 a, b, c, d;
    a.x = h0; a.y = h1; b.x = h2; b.y = h3;
    c.x = m0; c.y = m1; d.x = m2; d.y = m3;
    hi[2 * i] = a;  hi[2 * i + 1] = b;
    mid[2 * i] = c; mid[2 * i + 1] = d;
}

// ---------------------------------------------------------------------------
// Prepass 2: W [K x N] fp32 -> W^T [N x K] bf16 (hi, mid).
// ---------------------------------------------------------------------------
__global__ __launch_bounds__(256)
void split_transpose(const float* __restrict__ W,
                     __nv_bfloat16* __restrict__ hi,
                     __nv_bfloat16* __restrict__ mid, int K, int N)
{
    __shared__ float s[32][33];
    int n0 = blockIdx.x * 32;
    int k0 = blockIdx.y * 32;
    int tx = threadIdx.x, ty = threadIdx.y;
    #pragma unroll
    for (int i = 0; i < 4; i++) {
        int kk = ty + 8 * i;
        s[kk][tx] = W[(size_t)(k0 + kk) * N + n0 + tx];
    }
    __syncthreads();
    #pragma unroll
    for (int i = 0; i < 4; i++) {
        int nn = ty + 8 * i;
        float v = s[tx][nn];
        __nv_bfloat16 h = __float2bfloat16_rn(v);
        __nv_bfloat16 m = __float2bfloat16_rn(v - __bfloat162float(h));
        size_t o = (size_t)(n0 + nn) * KDIM + k0 + tx;
        hi[o] = h;
        mid[o] = m;
    }
}

// ---------------------------------------------------------------------------
// mma.sync split-bf16 GEMM: C = Ahi.Bhi^T + Ahi.Bmid^T + Amid.Bhi^T + bias
//   A*: [M x 1024] bf16 row-major.  B*: [N x 1024] bf16 row-major (W^T).
// CTA 128x128, BK=32, 256 threads (8 warps, warp tile 32x64).
// cp.async double-buffered stages; 80B row pitch (ldmatrix conflict-free).
// Mainloop is #pragma unroll 1 to bound code size / ptxas time.
// ---------------------------------------------------------------------------
#define GBM 128
#define GBN 128
#define GBK 32
#define ROWB 80                        // smem row pitch (bytes) for 64B rows
#define TILE_SZ (128 * ROWB)           // 10240
#define STAGE_SZ (4 * TILE_SZ)         // 40960
#define SMEM_MMA (2 * STAGE_SZ)        // 81920

__device__ __forceinline__ void load_tile_async(uint32_t dst,
                                                const __nv_bfloat16* src,
                                                int row0, int k0, int t)
{
    #pragma unroll
    for (int f = t; f < 512; f += 256) {
        int row = f >> 2, q = f & 3;
        cp16(dst + row * ROWB + q * 16,
             src + (size_t)(row0 + row) * KDIM + k0 + q * 8);
    }
}

__global__ __launch_bounds__(256, 1)
void mma_gemm(const __nv_bfloat16* __restrict__ Ahi,
              const __nv_bfloat16* __restrict__ Amid,
              const __nv_bfloat16* __restrict__ Bhi,
              const __nv_bfloat16* __restrict__ Bmid,
              const float* __restrict__ bias, float* __restrict__ C, int ldN)
{
    extern __shared__ char smraw[];
    uint32_t sb = smem_u32(smraw);

    int t    = threadIdx.x;
    int lane = t & 31;
    int wid  = t >> 5;
    int wm   = wid & 3;                // m warp: 0..3  -> m offset wm*32
    int wn   = wid >> 2;               // n warp: 0..1  -> n offset wn*64
    int m0   = blockIdx.y * GBM;
    int n0   = blockIdx.x * GBN;

    // ldmatrix lane-address selectors
    int g  = lane >> 3;                // matrix group 0..3
    int lr = lane & 7;
    int aRow = ((g & 1) << 3) + lr;    // +8 for odd groups
    int aCol = (g >> 1) << 4;          // +16B for k+8
    int bRow = ((g >> 1) << 3) + lr;
    int bCol = (g & 1) << 4;

    float c[2][8][4];
    #pragma unroll
    for (int mi = 0; mi < 2; mi++)
        #pragma unroll
        for (int ng = 0; ng < 8; ng++)
            #pragma unroll
            for (int j = 0; j < 4; j++) c[mi][ng][j] = 0.0f;

    const int NCH = KDIM / GBK;        // 32 chunks

    // prologue: chunk 0 -> stage 0
    {
        uint32_t st = sb;
        load_tile_async(st,               Ahi,  m0, 0, t);
        load_tile_async(st + TILE_SZ,     Amid, m0, 0, t);
        load_tile_async(st + 2 * TILE_SZ, Bhi,  n0, 0, t);
        load_tile_async(st + 3 * TILE_SZ, Bmid, n0, 0, t);
        CP_COMMIT();
    }

    #pragma unroll 1
    for (int i = 0; i < NCH; i++) {
        uint32_t cur = sb + (i & 1) * STAGE_SZ;
        if (i + 1 < NCH) {
            uint32_t nst = sb + ((i + 1) & 1) * STAGE_SZ;
            int k0 = (i + 1) * GBK;
            load_tile_async(nst,               Ahi,  m0, k0, t);
            load_tile_async(nst + TILE_SZ,     Amid, m0, k0, t);
            load_tile_async(nst + 2 * TILE_SZ, Bhi,  n0, k0, t);
            load_tile_async(nst + 3 * TILE_SZ, Bmid, n0, k0, t);
            CP_COMMIT();
            CP_WAIT(1);                // chunk i complete
        } else {
            CP_WAIT(0);
        }
        __syncthreads();

        uint32_t AhiB = cur;
        uint32_t AmdB = cur + TILE_SZ;
        uint32_t BhiB = cur + 2 * TILE_SZ;
        uint32_t BmdB = cur + 3 * TILE_SZ;

        #pragma unroll
        for (int ks = 0; ks < 2; ks++) {
            int kb = ks * 32;          // byte offset of this k16 within row
            uint32_t aH[2][4], aM[2][4], bH[4][4], bM[4][4];

            // A-hi fragments (2 m16 tiles)
            #pragma unroll
            for (int mi = 0; mi < 2; mi++)
                ldsm4(aH[mi], AhiB + (wm * 32 + mi * 16 + aRow) * ROWB + kb + aCol);
            // B-hi fragments (4 x4 = 8 n-groups)
            #pragma unroll
            for (int nb = 0; nb < 4; nb++)
                ldsm4(bH[nb], BhiB + (wn * 64 + nb * 16 + bRow) * ROWB + kb + bCol);
            // pass 1: hi*hi
            #pragma unroll
            for (int mi = 0; mi < 2; mi++)
                #pragma unroll
                for (int ng = 0; ng < 8; ng++)
                    mma16816(c[mi][ng], aH[mi], &bH[ng >> 1][(ng & 1) * 2]);

            // B-mid fragments; pass 2: hi*mid
            #pragma unroll
            for (int nb = 0; nb < 4; nb++)
                ldsm4(bM[nb], BmdB + (wn * 64 + nb * 16 + bRow) * ROWB + kb + bCol);
            #pragma unroll
            for (int mi = 0; mi < 2; mi++)
                #pragma unroll
                for (int ng = 0; ng < 8; ng++)
                    mma16816(c[mi][ng], aH[mi], &bM[ng >> 1][(ng & 1) * 2]);

            // A-mid fragments; pass 3: mid*hi
            #pragma unroll
            for (int mi = 0; mi < 2; mi++)
                ldsm4(aM[mi], AmdB + (wm * 32 + mi * 16 + aRow) * ROWB + kb + aCol);
            #pragma unroll
            for (int mi = 0; mi < 2; mi++)
                #pragma unroll
                for (int ng = 0; ng < 8; ng++)
                    mma16816(c[mi][ng], aM[mi], &bH[ng >> 1][(ng & 1) * 2]);
        }
        __syncthreads();
    }

    // epilogue: C frag layout: c0,c1 -> (row r, cols cg,cg+1); c2,c3 -> row r+8
    int r  = lane >> 2;
    int cg = (lane & 3) * 2;
    #pragma unroll
    for (int mi = 0; mi < 2; mi++) {
        #pragma unroll
        for (int ng = 0; ng < 8; ng++) {
            int gn  = n0 + wn * 64 + ng * 8 + cg;
            float2 bb = *(const float2*)(bias + gn);
            int gm  = m0 + wm * 32 + mi * 16 + r;
            float2 o0, o1;
            o0.x = c[mi][ng][0] + bb.x;  o0.y = c[mi][ng][1] + bb.y;
            o1.x = c[mi][ng][2] + bb.x;  o1.y = c[mi][ng][3] + bb.y;
            *(float2*)(C + (size_t)gm * ldN + gn)       = o0;
            *(float2*)(C + (size_t)(gm + 8) * ldN + gn) = o1;
        }
    }
}

// ---------------------------------------------------------------------------
// Causal flash attention (round-3 design, measured ~605us).
// ---------------------------------------------------------------------------
__global__ __launch_bounds__(128, 4)
void attn_kernel(const float* __restrict__ qkv, float* __restrict__ ctx)
{
    __shared__ float qs[64 * 64];
    __shared__ float kps[64 * 64];
    __shared__ float vsm[64 * 64];

    int qt = (int)gridDim.x - 1 - (int)blockIdx.x;
    int h  = blockIdx.y;
    int b  = blockIdx.z;
    int t  = threadIdx.x;
    int ty = t >> 4;
    int tx = t & 15;

    {
        int row = t >> 1;
        int dh  = (t & 1) * 32;
        const float* qr = qkv + (size_t)(b * SEQ + qt * 64 + row) * QKV_N
                        + h * HEAD_D + dh;
        #pragma unroll
        for (int i = 0; i < 8; i++) {
            float4 v = *(const float4*)(qr + 4 * i);
            int d = dh + 4 * i;
            qs[(d + 0) * 64 + row] = v.x * ATTN_SCALE;
            qs[(d + 1) * 64 + row] = v.y * ATTN_SCALE;
            qs[(d + 2) * 64 + row] = v.z * ATTN_SCALE;
            qs[(d + 3) * 64 + row] = v.w * ATTN_SCALE;
        }
    }

    float o[8][4];
    float m[8], l[8];
    #pragma unroll
    for (int i = 0; i < 8; i++) {
        m[i] = -CUDART_INF_F;
        l[i] = 0.0f;
        #pragma unroll
        for (int j = 0; j < 4; j++) o[i][j] = 0.0f;
    }

    #pragma unroll 1
    for (int kt = 0; kt <= qt; kt++) {
        __syncthreads();
        {
            int key = t >> 1;
            int dh  = (t & 1) * 32;
            const float* kr = qkv + (size_t)(b * SEQ + kt * 64 + key) * QKV_N
                            + HIDDEN + h * HEAD_D + dh;
            #pragma unroll
            for (int i = 0; i < 8; i++) {
                float4 v = *(const float4*)(kr + 4 * i);
                int d = dh + 4 * i;
                kps[(d + 0) * 64 + key] = v.x;
                kps[(d + 1) * 64 + key] = v.y;
                kps[(d + 2) * 64 + key] = v.z;
                kps[(d + 3) * 64 + key] = v.w;
            }
        }
        {
            #pragma unroll
            for (int i = 0; i < 8; i++) {
                int cidx = t + 128 * i;
                int key = cidx >> 4;
                int d0  = (cidx & 15) * 4;
                const float* vr = qkv + (size_t)(b * SEQ + kt * 64 + key) * QKV_N
                                + 2 * HIDDEN + h * HEAD_D + d0;
                *(float4*)&vsm[key * 64 + d0] = *(const float4*)vr;
            }
        }
        __syncthreads();

        float s[8][4];
        #pragma unroll
        for (int i = 0; i < 8; i++)
            #pragma unroll
            for (int j = 0; j < 4; j++) s[i][j] = 0.0f;

        #pragma unroll 4
        for (int d = 0; d < 64; d++) {
            float4 b4 = *(const float4*)&kps[d * 64 + tx * 4];
            float4 a0 = *(const float4*)&qs[d * 64 + ty * 8];
            float4 a1 = *(const float4*)&qs[d * 64 + ty * 8 + 4];
            float av[8] = {a0.x, a0.y, a0.z, a0.w, a1.x, a1.y, a1.z, a1.w};
            float bv[4] = {b4.x, b4.y, b4.z, b4.w};
            #pragma unroll
            for (int i = 0; i < 8; i++)
                #pragma unroll
                for (int j = 0; j < 4; j++)
                    s[i][j] = fmaf(av[i], bv[j], s[i][j]);
        }

        if (kt == qt) {
            #pragma unroll
            for (int i = 0; i < 8; i++)
                #pragma unroll
                for (int j = 0; j < 4; j++)
                    if (tx * 4 + j > ty * 8 + i) s[i][j] = -CUDART_INF_F;
        }

        #pragma unroll
        for (int i = 0; i < 8; i++) {
            float tm = fmaxf(fmaxf(s[i][0], s[i][1]), fmaxf(s[i][2], s[i][3]));
            tm = fmaxf(tm, __shfl_xor_sync(0xffffffffu, tm, 1));
            tm = fmaxf(tm, __shfl_xor_sync(0xffffffffu, tm, 2));
            tm = fmaxf(tm, __shfl_xor_sync(0xffffffffu, tm, 4));
            tm = fmaxf(tm, __shfl_xor_sync(0xffffffffu, tm, 8));
            float mn   = fmaxf(m[i], tm);
            float corr = __expf(m[i] - mn);
            m[i] = mn;
            float rs = 0.0f;
            #pragma unroll
            for (int j = 0; j < 4; j++) {
                float p = __expf(s[i][j] - mn);
                s[i][j] = p;
                rs += p;
            }
            l[i] = l[i] * corr + rs;
            #pragma unroll
            for (int j = 0; j < 4; j++) o[i][j] *= corr;
        }

        __syncthreads();

        #pragma unroll
        for (int i = 0; i < 8; i++) {
            float4 pv = make_float4(s[i][0], s[i][1], s[i][2], s[i][3]);
            *(float4*)&kps[(ty * 8 + i) * 64 + tx * 4] = pv;
        }
        __syncthreads();

        #pragma unroll 2
        for (int k = 0; k < 64; k++) {
            float4 b4 = *(const float4*)&vsm[k * 64 + tx * 4];
            float av[8];
            #pragma unroll
            for (int i = 0; i < 8; i++)
                av[i] = kps[(ty * 8 + i) * 64 + k];
            #pragma unroll
            for (int i = 0; i < 8; i++) {
                o[i][0] = fmaf(av[i], b4.x, o[i][0]);
                o[i][1] = fmaf(av[i], b4.y, o[i][1]);
                o[i][2] = fmaf(av[i], b4.z, o[i][2]);
                o[i][3] = fmaf(av[i], b4.w, o[i][3]);
            }
        }
    }

    #pragma unroll
    for (int i = 0; i < 8; i++) {
        float li = l[i];
        li += __shfl_xor_sync(0xffffffffu, li, 1);
        li += __shfl_xor_sync(0xffffffffu, li, 2);
        li += __shfl_xor_sync(0xffffffffu, li, 4);
        li += __shfl_xor_sync(0xffffffffu, li, 8);
        float inv = 1.0f / li;
        int row = qt * 64 + ty * 8 + i;
        float4 ov;
        ov.x = o[i][0] * inv;
        ov.y = o[i][1] * inv;
        ov.z = o[i][2] * inv;
        ov.w = o[i][3] * inv;
        *(float4*)(ctx + (size_t)(b * SEQ + row) * HIDDEN + h * HEAD_D + tx * 4) = ov;
    }
}

// ---------------------------------------------------------------------------
extern "C" void kernel_launch(void* const* d_in, const int* in_sizes, int n_in,
                              void* d_out, int out_size)
{
    const float* x     = (const float*)d_in[0];
    const float* W_qkv = (const float*)d_in[1];
    const float* b_qkv = (const float*)d_in[2];
    const float* W_out = (const float*)d_in[3];
    const float* b_out = (const float*)d_in[4];
    float* out = (float*)d_out;

    float *qkv, *ctx;
    __nv_bfloat16 *x_hi, *x_mid, *c_hi, *c_mid, *wq_hi, *wq_mid, *wo_hi, *wo_mid;
    cudaGetSymbolAddress((void**)&qkv,    g_qkv);
    cudaGetSymbolAddress((void**)&ctx,    g_ctx);
    cudaGetSymbolAddress((void**)&x_hi,   g_x_hi);
    cudaGetSymbolAddress((void**)&x_mid,  g_x_mid);
    cudaGetSymbolAddress((void**)&c_hi,   g_c_hi);
    cudaGetSymbolAddress((void**)&c_mid,  g_c_mid);
    cudaGetSymbolAddress((void**)&wq_hi,  g_wq_hi);
    cudaGetSymbolAddress((void**)&wq_mid, g_wq_mid);
    cudaGetSymbolAddress((void**)&wo_hi,  g_wo_hi);
    cudaGetSymbolAddress((void**)&wo_mid, g_wo_mid);

    cudaFuncSetAttribute(mma_gemm, cudaFuncAttributeMaxDynamicSharedMemorySize,
                         SMEM_MMA);

    // 1) split x -> bf16 hi/mid
    {
        int n4 = M_TOT * HIDDEN / 4;
        split_rows<<<(n4 + 255) / 256, 256>>>((const float4*)x,
                                              (__nv_bfloat162*)x_hi,
                                              (__nv_bfloat162*)x_mid, n4);
    }
    // 2) transpose+split W_qkv -> [3072][1024] bf16 hi/mid
    split_transpose<<<dim3(QKV_N / 32, KDIM / 32), dim3(32, 8)>>>(
        W_qkv, wq_hi, wq_mid, KDIM, QKV_N);
    // 3) QKV projection on tensor cores (mma.sync, 3-pass split-bf16)
    mma_gemm<<<dim3(QKV_N / GBN, M_TOT / GBM), 256, SMEM_MMA>>>(
        x_hi, x_mid, wq_hi, wq_mid, b_qkv, qkv, QKV_N);
    // 4) causal attention (fp32)
    {
        dim3 grid(SEQ / 64, HEADS, BATCH);
        attn_kernel<<<grid, 128>>>(qkv, ctx);
    }
    // 5) split ctx -> bf16 hi/mid
    {
        int n4 = M_TOT * HIDDEN / 4;
        split_rows<<<(n4 + 255) / 256, 256>>>((const float4*)ctx,
                                              (__nv_bfloat162*)c_hi,
                                              (__nv_bfloat162*)c_mid, n4);
    }
    // 6) transpose+split W_out -> [1024][1024] bf16 hi/mid
    split_transpose<<<dim3(HIDDEN / 32, KDIM / 32), dim3(32, 8)>>>(
        W_out, wo_hi, wo_mid, KDIM, HIDDEN);
    // 7) output projection on tensor cores
    mma_gemm<<<dim3(HIDDEN / GBN, M_TOT / GBM), 256, SMEM_MMA>>>(
        c_hi, c_mid, wo_hi, wo_mid, b_out, out, HIDDEN);
}

// round 8
// speedup vs baseline: 4.0670x; 1.6233x over previous
#include <cuda_runtime.h>
#include <cuda_bf16.h>
#include <math_constants.h>
#include <cstdint>

// Problem constants
#define BATCH   2
#define SEQ     2048
#define HIDDEN  1024
#define HEADS   16
#define HEAD_D  64
#define QKV_N   (3 * HIDDEN)          // 3072
#define M_TOT   (BATCH * SEQ)         // 4096
#define KDIM    1024
#define ATTN_SCALE 125.0f             // TEMP_K / sqrt(HEAD_D)
#define BH_TOT  (BATCH * HEADS)       // 32
#define ATT_ELEMS (BH_TOT * SEQ * HEAD_D)   // 4,194,304

// ---------------------------------------------------------------------------
// Scratch (__device__ globals per allocation-free rule)
// ---------------------------------------------------------------------------
__device__ float g_qkv[M_TOT * QKV_N];
__device__ float g_ctx[M_TOT * HIDDEN];
__device__ __nv_bfloat16 g_x_hi[M_TOT * HIDDEN];
__device__ __nv_bfloat16 g_x_mid[M_TOT * HIDDEN];
__device__ __nv_bfloat16 g_c_hi[M_TOT * HIDDEN];
__device__ __nv_bfloat16 g_c_mid[M_TOT * HIDDEN];
__device__ __nv_bfloat16 g_wq_hi[QKV_N * KDIM];
__device__ __nv_bfloat16 g_wq_mid[QKV_N * KDIM];
__device__ __nv_bfloat16 g_wo_hi[HIDDEN * KDIM];
__device__ __nv_bfloat16 g_wo_mid[HIDDEN * KDIM];
// attention operands (prepass output)
__device__ __nv_bfloat16 g_aq_hi[ATT_ELEMS];   // [bh][s][64], x125
__device__ __nv_bfloat16 g_aq_mid[ATT_ELEMS];
__device__ __nv_bfloat16 g_ak_hi[ATT_ELEMS];   // [bh][s][64]
__device__ __nv_bfloat16 g_ak_mid[ATT_ELEMS];
__device__ __nv_bfloat16 g_avt_hi[ATT_ELEMS];  // [bh][d=64][s=2048]
__device__ __nv_bfloat16 g_avt_mid[ATT_ELEMS];

// ---------------------------------------------------------------------------
__device__ __forceinline__ uint32_t smem_u32(const void* p) {
    uint32_t a;
    asm("{ .reg .u64 t; cvta.to.shared.u64 t, %1; cvt.u32.u64 %0, t; }"
        : "=r"(a) : "l"(p));
    return a;
}

__device__ __forceinline__ void cp16(uint32_t dst, const void* src) {
    asm volatile("cp.async.cg.shared.global [%0], [%1], 16;"
                 :: "r"(dst), "l"(src) : "memory");
}
#define CP_COMMIT() asm volatile("cp.async.commit_group;" ::: "memory")
#define CP_WAIT(n)  asm volatile("cp.async.wait_group %0;" :: "n"(n) : "memory")

__device__ __forceinline__ void ldsm4(uint32_t* r, uint32_t addr) {
    asm volatile("ldmatrix.sync.aligned.m8n8.x4.shared.b16 {%0,%1,%2,%3}, [%4];"
                 : "=r"(r[0]), "=r"(r[1]), "=r"(r[2]), "=r"(r[3]) : "r"(addr));
}

__device__ __forceinline__ void mma16816(float* c, const uint32_t* a,
                                         const uint32_t* b) {
    asm volatile(
        "mma.sync.aligned.m16n8k16.row.col.f32.bf16.bf16.f32 "
        "{%0,%1,%2,%3}, {%4,%5,%6,%7}, {%8,%9}, {%0,%1,%2,%3};"
        : "+f"(c[0]), "+f"(c[1]), "+f"(c[2]), "+f"(c[3])
        : "r"(a[0]), "r"(a[1]), "r"(a[2]), "r"(a[3]), "r"(b[0]), "r"(b[1]));
}

// pack two floats to bf16x2 (lo in low half) + residual pair
__device__ __forceinline__ void split_pk(float p0, float p1,
                                         uint32_t& hi, uint32_t& mid) {
    __nv_bfloat16 h0 = __float2bfloat16_rn(p0);
    __nv_bfloat16 h1 = __float2bfloat16_rn(p1);
    __nv_bfloat162 hv; hv.x = h0; hv.y = h1;
    hi = *reinterpret_cast<uint32_t*>(&hv);
    __nv_bfloat162 mv = __floats2bfloat162_rn(p0 - __bfloat162float(h0),
                                              p1 - __bfloat162float(h1));
    mid = *reinterpret_cast<uint32_t*>(&mv);
}

// ---------------------------------------------------------------------------
// Prepass 1: elementwise fp32 -> bf16 (hi, mid) split.
// ---------------------------------------------------------------------------
__global__ __launch_bounds__(256)
void split_rows(const float4* __restrict__ src,
                __nv_bfloat162* __restrict__ hi,
                __nv_bfloat162* __restrict__ mid, int n4)
{
    int i = blockIdx.x * blockDim.x + threadIdx.x;
    if (i >= n4) return;
    float4 v = src[i];
    __nv_bfloat16 h0 = __float2bfloat16_rn(v.x);
    __nv_bfloat16 h1 = __float2bfloat16_rn(v.y);
    __nv_bfloat16 h2 = __float2bfloat16_rn(v.z);
    __nv_bfloat16 h3 = __float2bfloat16_rn(v.w);
    __nv_bfloat16 m0 = __float2bfloat16_rn(v.x - __bfloat162float(h0));
    __nv_bfloat16 m1 = __float2bfloat16_rn(v.y - __bfloat162float(h1));
    __nv_bfloat16 m2 = __float2bfloat16_rn(v.z - __bfloat162float(h2));
    __nv_bfloat16 m3 = __float2bfloat16_rn(v.w - __bfloat162float(h3));
    __nv_bfloat162 a, b, c, d;
    a.x = h0; a.y = h1; b.x = h2; b.y = h3;
    c.x = m0; c.y = m1; d.x = m2; d.y = m3;
    hi[2 * i] = a;  hi[2 * i + 1] = b;
    mid[2 * i] = c; mid[2 * i + 1] = d;
}

// ---------------------------------------------------------------------------
// Prepass 2: W [K x N] fp32 -> W^T [N x K] bf16 (hi, mid).
// ---------------------------------------------------------------------------
__global__ __launch_bounds__(256)
void split_transpose(const float* __restrict__ W,
                     __nv_bfloat16* __restrict__ hi,
                     __nv_bfloat16* __restrict__ mid, int K, int N)
{
    __shared__ float s[32][33];
    int n0 = blockIdx.x * 32;
    int k0 = blockIdx.y * 32;
    int tx = threadIdx.x, ty = threadIdx.y;
    #pragma unroll
    for (int i = 0; i < 4; i++) {
        int kk = ty + 8 * i;
        s[kk][tx] = W[(size_t)(k0 + kk) * N + n0 + tx];
    }
    __syncthreads();
    #pragma unroll
    for (int i = 0; i < 4; i++) {
        int nn = ty + 8 * i;
        float v = s[tx][nn];
        __nv_bfloat16 h = __float2bfloat16_rn(v);
        __nv_bfloat16 m = __float2bfloat16_rn(v - __bfloat162float(h));
        size_t o = (size_t)(n0 + nn) * KDIM + k0 + tx;
        hi[o] = h;
        mid[o] = m;
    }
}

// ---------------------------------------------------------------------------
// Prepass 3: qkv fp32 -> attention operands (Q x125 hi/mid, K hi/mid, Vt hi/mid)
// grid (SEQ/64, HEADS, BATCH), block 256.
// ---------------------------------------------------------------------------
__global__ __launch_bounds__(256)
void attn_prep(const float* __restrict__ qkv,
               __nv_bfloat16* __restrict__ qh, __nv_bfloat16* __restrict__ qm,
               __nv_bfloat16* __restrict__ kh, __nv_bfloat16* __restrict__ km,
               __nv_bfloat16* __restrict__ vth, __nv_bfloat16* __restrict__ vtm)
{
    __shared__ float vs[64][65];
    int st = blockIdx.x * 64;
    int h  = blockIdx.y;
    int b  = blockIdx.z;
    int bh = b * HEADS + h;
    int t  = threadIdx.x;

    #pragma unroll
    for (int i = 0; i < 16; i++) {
        int e   = t + 256 * i;       // 0..4095
        int row = e >> 6;
        int d   = e & 63;
        const float* base = qkv + (size_t)(b * SEQ + st + row) * QKV_N + h * HEAD_D + d;
        size_t o = ((size_t)bh * SEQ + st + row) * HEAD_D + d;
        float q = base[0] * ATTN_SCALE;
        __nv_bfloat16 qhi = __float2bfloat16_rn(q);
        qh[o] = qhi;
        qm[o] = __float2bfloat16_rn(q - __bfloat162float(qhi));
        float k = base[HIDDEN];
        __nv_bfloat16 khi = __float2bfloat16_rn(k);
        kh[o] = khi;
        km[o] = __float2bfloat16_rn(k - __bfloat162float(khi));
        vs[row][d] = base[2 * HIDDEN];
    }
    __syncthreads();
    #pragma unroll
    for (int i = 0; i < 16; i++) {
        int e    = t + 256 * i;
        int drow = e >> 6;           // d
        int scol = e & 63;           // s within chunk
        float v = vs[scol][drow];    // transposed read
        __nv_bfloat16 vhi = __float2bfloat16_rn(v);
        size_t o = ((size_t)bh * HEAD_D + drow) * SEQ + st + scol;
        vth[o] = vhi;
        vtm[o] = __float2bfloat16_rn(v - __bfloat162float(vhi));
    }
}

// ---------------------------------------------------------------------------
// mma.sync split-bf16 GEMM (unchanged from round 7; passed).
// ---------------------------------------------------------------------------
#define GBM 128
#define GBN 128
#define GBK 32
#define ROWB 80
#define TILE_SZ (128 * ROWB)
#define STAGE_SZ (4 * TILE_SZ)
#define SMEM_MMA (2 * STAGE_SZ)

__device__ __forceinline__ void load_tile_async(uint32_t dst,
                                                const __nv_bfloat16* src,
                                                int row0, int k0, int t)
{
    #pragma unroll
    for (int f = t; f < 512; f += 256) {
        int row = f >> 2, q = f & 3;
        cp16(dst + row * ROWB + q * 16,
             src + (size_t)(row0 + row) * KDIM + k0 + q * 8);
    }
}

__global__ __launch_bounds__(256, 1)
void mma_gemm(const __nv_bfloat16* __restrict__ Ahi,
              const __nv_bfloat16* __restrict__ Amid,
              const __nv_bfloat16* __restrict__ Bhi,
              const __nv_bfloat16* __restrict__ Bmid,
              const float* __restrict__ bias, float* __restrict__ C, int ldN)
{
    extern __shared__ char smraw[];
    uint32_t sb = smem_u32(smraw);

    int t    = threadIdx.x;
    int lane = t & 31;
    int wid  = t >> 5;
    int wm   = wid & 3;
    int wn   = wid >> 2;
    int m0   = blockIdx.y * GBM;
    int n0   = blockIdx.x * GBN;

    int g  = lane >> 3;
    int lr = lane & 7;
    int aRow = ((g & 1) << 3) + lr;
    int aCol = (g >> 1) << 4;
    int bRow = ((g >> 1) << 3) + lr;
    int bCol = (g & 1) << 4;

    float c[2][8][4];
    #pragma unroll
    for (int mi = 0; mi < 2; mi++)
        #pragma unroll
        for (int ng = 0; ng < 8; ng++)
            #pragma unroll
            for (int j = 0; j < 4; j++) c[mi][ng][j] = 0.0f;

    const int NCH = KDIM / GBK;

    {
        uint32_t st = sb;
        load_tile_async(st,               Ahi,  m0, 0, t);
        load_tile_async(st + TILE_SZ,     Amid, m0, 0, t);
        load_tile_async(st + 2 * TILE_SZ, Bhi,  n0, 0, t);
        load_tile_async(st + 3 * TILE_SZ, Bmid, n0, 0, t);
        CP_COMMIT();
    }

    #pragma unroll 1
    for (int i = 0; i < NCH; i++) {
        uint32_t cur = sb + (i & 1) * STAGE_SZ;
        if (i + 1 < NCH) {
            uint32_t nst = sb + ((i + 1) & 1) * STAGE_SZ;
            int k0 = (i + 1) * GBK;
            load_tile_async(nst,               Ahi,  m0, k0, t);
            load_tile_async(nst + TILE_SZ,     Amid, m0, k0, t);
            load_tile_async(nst + 2 * TILE_SZ, Bhi,  n0, k0, t);
            load_tile_async(nst + 3 * TILE_SZ, Bmid, n0, k0, t);
            CP_COMMIT();
            CP_WAIT(1);
        } else {
            CP_WAIT(0);
        }
        __syncthreads();

        uint32_t AhiB = cur;
        uint32_t AmdB = cur + TILE_SZ;
        uint32_t BhiB = cur + 2 * TILE_SZ;
        uint32_t BmdB = cur + 3 * TILE_SZ;

        #pragma unroll
        for (int ks = 0; ks < 2; ks++) {
            int kb = ks * 32;
            uint32_t aH[2][4], aM[2][4], bH[4][4], bM[4][4];

            #pragma unroll
            for (int mi = 0; mi < 2; mi++)
                ldsm4(aH[mi], AhiB + (wm * 32 + mi * 16 + aRow) * ROWB + kb + aCol);
            #pragma unroll
            for (int nb = 0; nb < 4; nb++)
                ldsm4(bH[nb], BhiB + (wn * 64 + nb * 16 + bRow) * ROWB + kb + bCol);
            #pragma unroll
            for (int mi = 0; mi < 2; mi++)
                #pragma unroll
                for (int ng = 0; ng < 8; ng++)
                    mma16816(c[mi][ng], aH[mi], &bH[ng >> 1][(ng & 1) * 2]);

            #pragma unroll
            for (int nb = 0; nb < 4; nb++)
                ldsm4(bM[nb], BmdB + (wn * 64 + nb * 16 + bRow) * ROWB + kb + bCol);
            #pragma unroll
            for (int mi = 0; mi < 2; mi++)
                #pragma unroll
                for (int ng = 0; ng < 8; ng++)
                    mma16816(c[mi][ng], aH[mi], &bM[ng >> 1][(ng & 1) * 2]);

            #pragma unroll
            for (int mi = 0; mi < 2; mi++)
                ldsm4(aM[mi], AmdB + (wm * 32 + mi * 16 + aRow) * ROWB + kb + aCol);
            #pragma unroll
            for (int mi = 0; mi < 2; mi++)
                #pragma unroll
                for (int ng = 0; ng < 8; ng++)
                    mma16816(c[mi][ng], aM[mi], &bH[ng >> 1][(ng & 1) * 2]);
        }
        __syncthreads();
    }

    int r  = lane >> 2;
    int cg = (lane & 3) * 2;
    #pragma unroll
    for (int mi = 0; mi < 2; mi++) {
        #pragma unroll
        for (int ng = 0; ng < 8; ng++) {
            int gn  = n0 + wn * 64 + ng * 8 + cg;
            float2 bb = *(const float2*)(bias + gn);
            int gm  = m0 + wm * 32 + mi * 16 + r;
            float2 o0, o1;
            o0.x = c[mi][ng][0] + bb.x;  o0.y = c[mi][ng][1] + bb.y;
            o1.x = c[mi][ng][2] + bb.x;  o1.y = c[mi][ng][3] + bb.y;
            *(float2*)(C + (size_t)gm * ldN + gn)       = o0;
            *(float2*)(C + (size_t)(gm + 8) * ldN + gn) = o1;
        }
    }
}

// ---------------------------------------------------------------------------
// Tensor-core causal flash attention.
// grid (16 qtiles, HEADS, BATCH), 256 threads (8 warps).
// Warp w owns rows q0 + w*16 .. +15, full 64-key width per tile.
// Q A-frags hoisted to registers; S->P split packed register-direct into
// A-frags for PV; K/V tiles cp.async double-buffered; 144B smem pitch.
// ---------------------------------------------------------------------------
#define AP 144                          // smem row pitch (bytes)
#define AQ_SZ   (128 * AP)              // 18432 per Q array
#define AKV_TSZ (64 * AP)               // 9216 per tile
#define AKV_SSZ (4 * AKV_TSZ)           // 36864 per stage
#define SMEM_ATT (2 * AQ_SZ + 2 * AKV_SSZ)   // 110592

__device__ __forceinline__ void load_kv_tiles(uint32_t dst,
    const __nv_bfloat16* kh, const __nv_bfloat16* km,
    const __nv_bfloat16* vth, const __nv_bfloat16* vtm,
    int bh, int k0, int t)
{
    #pragma unroll
    for (int i = 0; i < 2; i++) {
        int f = t + 256 * i;           // 0..511
        int row = f >> 3, ch = f & 7;
        size_t ko = ((size_t)bh * SEQ + k0 + row) * HEAD_D + ch * 8;
        size_t vo = ((size_t)bh * HEAD_D + row) * SEQ + k0 + ch * 8;
        uint32_t so = row * AP + ch * 16;
        cp16(dst + so,                kh  + ko);
        cp16(dst + AKV_TSZ + so,      km  + ko);
        cp16(dst + 2 * AKV_TSZ + so,  vth + vo);
        cp16(dst + 3 * AKV_TSZ + so,  vtm + vo);
    }
}

__global__ __launch_bounds__(256, 1)
void attn_mma(const __nv_bfloat16* __restrict__ qhp,
              const __nv_bfloat16* __restrict__ qmp,
              const __nv_bfloat16* __restrict__ khp,
              const __nv_bfloat16* __restrict__ kmp,
              const __nv_bfloat16* __restrict__ vthp,
              const __nv_bfloat16* __restrict__ vtmp,
              float* __restrict__ ctx)
{
    extern __shared__ char smraw[];
    uint32_t sb  = smem_u32(smraw);
    uint32_t QB  = sb;                 // Qhi, Qmid
    uint32_t STG = sb + 2 * AQ_SZ;

    int qt = (int)gridDim.x - 1 - (int)blockIdx.x;   // heavy first
    int h  = blockIdx.y;
    int b  = blockIdx.z;
    int bh = b * HEADS + h;
    int q0 = qt * 128;
    int t    = threadIdx.x;
    int lane = t & 31;
    int wid  = t >> 5;                 // 0..7

    int g  = lane >> 3;
    int lr = lane & 7;
    int aRow = ((g & 1) << 3) + lr;
    int aCol = (g >> 1) << 4;
    int bRow = ((g >> 1) << 3) + lr;
    int bCol = (g & 1) << 4;

    // async-load Q tiles (hi, mid): 128 rows x 8 chunks each
    {
        const __nv_bfloat16* qsrc[2] = {qhp, qmp};
        #pragma unroll
        for (int a = 0; a < 2; a++) {
            const __nv_bfloat16* p = qsrc[a] + ((size_t)bh * SEQ + q0) * HEAD_D;
            #pragma unroll
            for (int i = 0; i < 4; i++) {
                int f = t + 256 * i;   // 0..1023
                int row = f >> 3, ch = f & 7;
                cp16(QB + a * AQ_SZ + row * AP + ch * 16, p + row * HEAD_D + ch * 8);
            }
        }
        CP_COMMIT();
    }
    // prefetch KV tile 0
    load_kv_tiles(STG, khp, kmp, vthp, vtmp, bh, 0, t);
    CP_COMMIT();

    CP_WAIT(1);                        // Q resident
    __syncthreads();

    // hoist Q A-frags
    uint32_t qfh[4][4], qfm[4][4];
    #pragma unroll
    for (int ks = 0; ks < 4; ks++) {
        ldsm4(qfh[ks], QB +            (wid * 16 + aRow) * AP + ks * 32 + aCol);
        ldsm4(qfm[ks], QB + AQ_SZ +    (wid * 16 + aRow) * AP + ks * 32 + aCol);
    }

    float o[8][4];
    #pragma unroll
    for (int nb = 0; nb < 8; nb++)
        #pragma unroll
        for (int j = 0; j < 4; j++) o[nb][j] = 0.0f;
    float m0 = -CUDART_INF_F, m1 = -CUDART_INF_F;
    float l0 = 0.0f, l1 = 0.0f;

    int r0g = q0 + wid * 16 + (lane >> 2);
    const int nkt = qt * 2 + 2;

    #pragma unroll 1
    for (int kt = 0; kt < nkt; kt++) {
        uint32_t cur = STG + (kt & 1) * AKV_SSZ;
        if (kt + 1 < nkt) {
            load_kv_tiles(STG + ((kt + 1) & 1) * AKV_SSZ,
                          khp, kmp, vthp, vtmp, bh, (kt + 1) * 64, t);
            CP_COMMIT();
            CP_WAIT(1);
        } else {
            CP_WAIT(0);
        }
        __syncthreads();

        // ---- S = QK^T, 3-pass split ----
        float s[8][4];
        #pragma unroll
        for (int nb = 0; nb < 8; nb++)
            #pragma unroll
            for (int j = 0; j < 4; j++) s[nb][j] = 0.0f;

        #pragma unroll
        for (int ks = 0; ks < 4; ks++) {
            uint32_t bkh[4][4], bkm[4][4];
            #pragma unroll
            for (int n4 = 0; n4 < 4; n4++)
                ldsm4(bkh[n4], cur + (n4 * 16 + bRow) * AP + ks * 32 + bCol);
            #pragma unroll
            for (int n4 = 0; n4 < 4; n4++)
                ldsm4(bkm[n4], cur + AKV_TSZ + (n4 * 16 + bRow) * AP + ks * 32 + bCol);
            #pragma unroll
            for (int nb = 0; nb < 8; nb++) {
                mma16816(s[nb], qfh[ks], &bkh[nb >> 1][(nb & 1) * 2]);
                mma16816(s[nb], qfh[ks], &bkm[nb >> 1][(nb & 1) * 2]);
                mma16816(s[nb], qfm[ks], &bkh[nb >> 1][(nb & 1) * 2]);
            }
        }

        // ---- causal mask (only tiles crossing the diagonal for this warp) ----
        if (kt * 64 + 63 > q0 + wid * 16) {
            #pragma unroll
            for (int nb = 0; nb < 8; nb++) {
                int gc = kt * 64 + nb * 8 + (lane & 3) * 2;
                if (gc + 0 > r0g)     s[nb][0] = -CUDART_INF_F;
                if (gc + 1 > r0g)     s[nb][1] = -CUDART_INF_F;
                if (gc + 0 > r0g + 8) s[nb][2] = -CUDART_INF_F;
                if (gc + 1 > r0g + 8) s[nb][3] = -CUDART_INF_F;
            }
        }

        // ---- online softmax (rows r0g, r0g+8; quad-reduce max) ----
        float tm0 = -CUDART_INF_F, tm1 = -CUDART_INF_F;
        #pragma unroll
        for (int nb = 0; nb < 8; nb++) {
            tm0 = fmaxf(tm0, fmaxf(s[nb][0], s[nb][1]));
            tm1 = fmaxf(tm1, fmaxf(s[nb][2], s[nb][3]));
        }
        tm0 = fmaxf(tm0, __shfl_xor_sync(0xffffffffu, tm0, 1));
        tm0 = fmaxf(tm0, __shfl_xor_sync(0xffffffffu, tm0, 2));
        tm1 = fmaxf(tm1, __shfl_xor_sync(0xffffffffu, tm1, 1));
        tm1 = fmaxf(tm1, __shfl_xor_sync(0xffffffffu, tm1, 2));
        float mn0 = fmaxf(m0, tm0), mn1 = fmaxf(m1, tm1);
        float c0 = __expf(m0 - mn0), c1 = __expf(m1 - mn1);
        m0 = mn0; m1 = mn1;
        float rs0 = 0.0f, rs1 = 0.0f;
        #pragma unroll
        for (int nb = 0; nb < 8; nb++) {
            s[nb][0] = __expf(s[nb][0] - mn0);
            s[nb][1] = __expf(s[nb][1] - mn0);
            s[nb][2] = __expf(s[nb][2] - mn1);
            s[nb][3] = __expf(s[nb][3] - mn1);
            rs0 += s[nb][0] + s[nb][1];
            rs1 += s[nb][2] + s[nb][3];
        }
        l0 = l0 * c0 + rs0;
        l1 = l1 * c1 + rs1;
        #pragma unroll
        for (int nb = 0; nb < 8; nb++) {
            o[nb][0] *= c0; o[nb][1] *= c0;
            o[nb][2] *= c1; o[nb][3] *= c1;
        }

        // ---- O += P V, 3-pass split; P packed register-direct as A-frags ----
        #pragma unroll
        for (int ks = 0; ks < 4; ks++) {
            uint32_t ah[4], am[4];
            split_pk(s[2 * ks][0],     s[2 * ks][1],     ah[0], am[0]);
            split_pk(s[2 * ks][2],     s[2 * ks][3],     ah[1], am[1]);
            split_pk(s[2 * ks + 1][0], s[2 * ks + 1][1], ah[2], am[2]);
            split_pk(s[2 * ks + 1][2], s[2 * ks + 1][3], ah[3], am[3]);

            uint32_t bvh[4][4], bvm[4][4];
            #pragma unroll
            for (int n4 = 0; n4 < 4; n4++)
                ldsm4(bvh[n4], cur + 2 * AKV_TSZ + (n4 * 16 + bRow) * AP + ks * 32 + bCol);
            #pragma unroll
            for (int n4 = 0; n4 < 4; n4++)
                ldsm4(bvm[n4], cur + 3 * AKV_TSZ + (n4 * 16 + bRow) * AP + ks * 32 + bCol);
            #pragma unroll
            for (int nb = 0; nb < 8; nb++) {
                mma16816(o[nb], ah, &bvh[nb >> 1][(nb & 1) * 2]);
                mma16816(o[nb], ah, &bvm[nb >> 1][(nb & 1) * 2]);
                mma16816(o[nb], am, &bvh[nb >> 1][(nb & 1) * 2]);
            }
        }
        __syncthreads();               // all reads of cur done before reuse
    }

    // ---- finalize ----
    l0 += __shfl_xor_sync(0xffffffffu, l0, 1);
    l0 += __shfl_xor_sync(0xffffffffu, l0, 2);
    l1 += __shfl_xor_sync(0xffffffffu, l1, 1);
    l1 += __shfl_xor_sync(0xffffffffu, l1, 2);
    float inv0 = 1.0f / l0, inv1 = 1.0f / l1;
    int cbase = h * HEAD_D + (lane & 3) * 2;
    #pragma unroll
    for (int nb = 0; nb < 8; nb++) {
        float2 w0, w1;
        w0.x = o[nb][0] * inv0; w0.y = o[nb][1] * inv0;
        w1.x = o[nb][2] * inv1; w1.y = o[nb][3] * inv1;
        *(float2*)(ctx + (size_t)(b * SEQ + r0g) * HIDDEN + cbase + nb * 8)       = w0;
        *(float2*)(ctx + (size_t)(b * SEQ + r0g + 8) * HIDDEN + cbase + nb * 8)   = w1;
    }
}

// ---------------------------------------------------------------------------
extern "C" void kernel_launch(void* const* d_in, const int* in_sizes, int n_in,
                              void* d_out, int out_size)
{
    const float* x     = (const float*)d_in[0];
    const float* W_qkv = (const float*)d_in[1];
    const float* b_qkv = (const float*)d_in[2];
    const float* W_out = (const float*)d_in[3];
    const float* b_out = (const float*)d_in[4];
    float* out = (float*)d_out;

    float *qkv, *ctx;
    __nv_bfloat16 *x_hi, *x_mid, *c_hi, *c_mid, *wq_hi, *wq_mid, *wo_hi, *wo_mid;
    __nv_bfloat16 *aqh, *aqm, *akh, *akm, *avh, *avm;
    cudaGetSymbolAddress((void**)&qkv,    g_qkv);
    cudaGetSymbolAddress((void**)&ctx,    g_ctx);
    cudaGetSymbolAddress((void**)&x_hi,   g_x_hi);
    cudaGetSymbolAddress((void**)&x_mid,  g_x_mid);
    cudaGetSymbolAddress((void**)&c_hi,   g_c_hi);
    cudaGetSymbolAddress((void**)&c_mid,  g_c_mid);
    cudaGetSymbolAddress((void**)&wq_hi,  g_wq_hi);
    cudaGetSymbolAddress((void**)&wq_mid, g_wq_mid);
    cudaGetSymbolAddress((void**)&wo_hi,  g_wo_hi);
    cudaGetSymbolAddress((void**)&wo_mid, g_wo_mid);
    cudaGetSymbolAddress((void**)&aqh,    g_aq_hi);
    cudaGetSymbolAddress((void**)&aqm,    g_aq_mid);
    cudaGetSymbolAddress((void**)&akh,    g_ak_hi);
    cudaGetSymbolAddress((void**)&akm,    g_ak_mid);
    cudaGetSymbolAddress((void**)&avh,    g_avt_hi);
    cudaGetSymbolAddress((void**)&avm,    g_avt_mid);

    cudaFuncSetAttribute(mma_gemm, cudaFuncAttributeMaxDynamicSharedMemorySize,
                         SMEM_MMA);
    cudaFuncSetAttribute(attn_mma, cudaFuncAttributeMaxDynamicSharedMemorySize,
                         SMEM_ATT);

    // 1) split x -> bf16 hi/mid
    {
        int n4 = M_TOT * HIDDEN / 4;
        split_rows<<<(n4 + 255) / 256, 256>>>((const float4*)x,
                                              (__nv_bfloat162*)x_hi,
                                              (__nv_bfloat162*)x_mid, n4);
    }
    // 2) transpose+split W_qkv
    split_transpose<<<dim3(QKV_N / 32, KDIM / 32), dim3(32, 8)>>>(
        W_qkv, wq_hi, wq_mid, KDIM, QKV_N);
    // 3) QKV projection (tensor cores)
    mma_gemm<<<dim3(QKV_N / GBN, M_TOT / GBM), 256, SMEM_MMA>>>(
        x_hi, x_mid, wq_hi, wq_mid, b_qkv, qkv, QKV_N);
    // 4) prep attention operands (split + Vt transpose)
    attn_prep<<<dim3(SEQ / 64, HEADS, BATCH), 256>>>(
        qkv, aqh, aqm, akh, akm, avh, avm);
    // 5) causal attention (tensor cores)
    attn_mma<<<dim3(SEQ / 128, HEADS, BATCH), 256, SMEM_ATT>>>(
        aqh, aqm, akh, akm, avh, avm, ctx);
    // 6) split ctx
    {
        int n4 = M_TOT * HIDDEN / 4;
        split_rows<<<(n4 + 255) / 256, 256>>>((const float4*)ctx,
                                              (__nv_bfloat162*)c_hi,
                                              (__nv_bfloat162*)c_mid, n4);
    }
    // 7) transpose+split W_out
    split_transpose<<<dim3(HIDDEN / 32, KDIM / 32), dim3(32, 8)>>>(
        W_out, wo_hi, wo_mid, KDIM, HIDDEN);
    // 8) output projection (tensor cores)
    mma_gemm<<<dim3(HIDDEN / GBN, M_TOT / GBM), 256, SMEM_MMA>>>(
        c_hi, c_mid, wo_hi, wo_mid, b_out, out, HIDDEN);
}

// round 11
// speedup vs baseline: 4.0845x; 1.0043x over previous
#include <cuda_runtime.h>
#include <cuda_bf16.h>
#include <math_constants.h>
#include <cstdint>

// Problem constants
#define BATCH   2
#define SEQ     2048
#define HIDDEN  1024
#define HEADS   16
#define HEAD_D  64
#define QKV_N   (3 * HIDDEN)          // 3072
#define M_TOT   (BATCH * SEQ)         // 4096
#define KDIM    1024
#define ATTN_SCALE 125.0f             // TEMP_K / sqrt(HEAD_D)
#define BH_TOT  (BATCH * HEADS)       // 32
#define ATT_ELEMS (BH_TOT * SEQ * HEAD_D)
#define SKIP_MARGIN 40.0f             // logit-units deadband for tile skip

// ---------------------------------------------------------------------------
// Scratch (__device__ globals per allocation-free rule)
// ---------------------------------------------------------------------------
__device__ float g_qkv[M_TOT * QKV_N];
__device__ __nv_bfloat16 g_x_hi[M_TOT * HIDDEN];
__device__ __nv_bfloat16 g_x_mid[M_TOT * HIDDEN];
__device__ __nv_bfloat16 g_c_hi[M_TOT * HIDDEN];
__device__ __nv_bfloat16 g_c_mid[M_TOT * HIDDEN];
__device__ __nv_bfloat16 g_wq_hi[QKV_N * KDIM];
__device__ __nv_bfloat16 g_wq_mid[QKV_N * KDIM];
__device__ __nv_bfloat16 g_wo_hi[HIDDEN * KDIM];
__device__ __nv_bfloat16 g_wo_mid[HIDDEN * KDIM];
__device__ __nv_bfloat16 g_aq_hi[ATT_ELEMS];
__device__ __nv_bfloat16 g_aq_mid[ATT_ELEMS];
__device__ __nv_bfloat16 g_ak_hi[ATT_ELEMS];
__device__ __nv_bfloat16 g_ak_mid[ATT_ELEMS];
__device__ __nv_bfloat16 g_avt_hi[ATT_ELEMS];
__device__ __nv_bfloat16 g_avt_mid[ATT_ELEMS];

// ---------------------------------------------------------------------------
__device__ __forceinline__ uint32_t smem_u32(const void* p) {
    uint32_t a;
    asm("{ .reg .u64 t; cvta.to.shared.u64 t, %1; cvt.u32.u64 %0, t; }"
        : "=r"(a) : "l"(p));
    return a;
}

__device__ __forceinline__ void cp16(uint32_t dst, const void* src) {
    asm volatile("cp.async.cg.shared.global [%0], [%1], 16;"
                 :: "r"(dst), "l"(src) : "memory");
}
#define CP_COMMIT() asm volatile("cp.async.commit_group;" ::: "memory")
#define CP_WAIT(n)  asm volatile("cp.async.wait_group %0;" :: "n"(n) : "memory")

__device__ __forceinline__ void ldsm4(uint32_t* r, uint32_t addr) {
    asm volatile("ldmatrix.sync.aligned.m8n8.x4.shared.b16 {%0,%1,%2,%3}, [%4];"
                 : "=r"(r[0]), "=r"(r[1]), "=r"(r[2]), "=r"(r[3]) : "r"(addr));
}

__device__ __forceinline__ void mma16816(float* c, const uint32_t* a,
                                         const uint32_t* b) {
    asm volatile(
        "mma.sync.aligned.m16n8k16.row.col.f32.bf16.bf16.f32 "
        "{%0,%1,%2,%3}, {%4,%5,%6,%7}, {%8,%9}, {%0,%1,%2,%3};"
        : "+f"(c[0]), "+f"(c[1]), "+f"(c[2]), "+f"(c[3])
        : "r"(a[0]), "r"(a[1]), "r"(a[2]), "r"(a[3]), "r"(b[0]), "r"(b[1]));
}

__device__ __forceinline__ void split_pk(float p0, float p1,
                                         uint32_t& hi, uint32_t& mid) {
    __nv_bfloat16 h0 = __float2bfloat16_rn(p0);
    __nv_bfloat16 h1 = __float2bfloat16_rn(p1);
    __nv_bfloat162 hv; hv.x = h0; hv.y = h1;
    hi = *reinterpret_cast<uint32_t*>(&hv);
    __nv_bfloat162 mv = __floats2bfloat162_rn(p0 - __bfloat162float(h0),
                                              p1 - __bfloat162float(h1));
    mid = *reinterpret_cast<uint32_t*>(&mv);
}

__device__ __forceinline__ void store_split2(__nv_bfloat16* hi,
                                             __nv_bfloat16* mid,
                                             size_t off, float a, float b) {
    __nv_bfloat162 h;
    h.x = __float2bfloat16_rn(a);
    h.y = __float2bfloat16_rn(b);
    *(__nv_bfloat162*)(hi + off) = h;
    __nv_bfloat162 m2 = __floats2bfloat162_rn(a - __bfloat162float(h.x),
                                              b - __bfloat162float(h.y));
    *(__nv_bfloat162*)(mid + off) = m2;
}

// ---------------------------------------------------------------------------
// Prepass 1: elementwise fp32 -> bf16 (hi, mid) split.
// ---------------------------------------------------------------------------
__global__ __launch_bounds__(256)
void split_rows(const float4* __restrict__ src,
                __nv_bfloat162* __restrict__ hi,
                __nv_bfloat162* __restrict__ mid, int n4)
{
    int i = blockIdx.x * blockDim.x + threadIdx.x;
    if (i >= n4) return;
    float4 v = src[i];
    __nv_bfloat16 h0 = __float2bfloat16_rn(v.x);
    __nv_bfloat16 h1 = __float2bfloat16_rn(v.y);
    __nv_bfloat16 h2 = __float2bfloat16_rn(v.z);
    __nv_bfloat16 h3 = __float2bfloat16_rn(v.w);
    __nv_bfloat16 m0 = __float2bfloat16_rn(v.x - __bfloat162float(h0));
    __nv_bfloat16 m1 = __float2bfloat16_rn(v.y - __bfloat162float(h1));
    __nv_bfloat16 m2 = __float2bfloat16_rn(v.z - __bfloat162float(h2));
    __nv_bfloat16 m3 = __float2bfloat16_rn(v.w - __bfloat162float(h3));
    __nv_bfloat162 a, b, c, d;
    a.x = h0; a.y = h1; b.x = h2; b.y = h3;
    c.x = m0; c.y = m1; d.x = m2; d.y = m3;
    hi[2 * i] = a;  hi[2 * i + 1] = b;
    mid[2 * i] = c; mid[2 * i + 1] = d;
}

// ---------------------------------------------------------------------------
// Prepass 2: W [K x N] fp32 -> W^T [N x K] bf16 (hi, mid).
// ---------------------------------------------------------------------------
__global__ __launch_bounds__(256)
void split_transpose(const float* __restrict__ W,
                     __nv_bfloat16* __restrict__ hi,
                     __nv_bfloat16* __restrict__ mid, int K, int N)
{
    __shared__ float s[32][33];
    int n0 = blockIdx.x * 32;
    int k0 = blockIdx.y * 32;
    int tx = threadIdx.x, ty = threadIdx.y;
    #pragma unroll
    for (int i = 0; i < 4; i++) {
        int kk = ty + 8 * i;
        s[kk][tx] = W[(size_t)(k0 + kk) * N + n0 + tx];
    }
    __syncthreads();
    #pragma unroll
    for (int i = 0; i < 4; i++) {
        int nn = ty + 8 * i;
        float v = s[tx][nn];
        __nv_bfloat16 h = __float2bfloat16_rn(v);
        __nv_bfloat16 m = __float2bfloat16_rn(v - __bfloat162float(h));
        size_t o = (size_t)(n0 + nn) * KDIM + k0 + tx;
        hi[o] = h;
        mid[o] = m;
    }
}

// ---------------------------------------------------------------------------
// Prepass 3: qkv fp32 -> attention operands.
// ---------------------------------------------------------------------------
__global__ __launch_bounds__(256)
void attn_prep(const float* __restrict__ qkv,
               __nv_bfloat16* __restrict__ qh, __nv_bfloat16* __restrict__ qm,
               __nv_bfloat16* __restrict__ kh, __nv_bfloat16* __restrict__ km,
               __nv_bfloat16* __restrict__ vth, __nv_bfloat16* __restrict__ vtm)
{
    __shared__ float vs[64][65];
    int st = blockIdx.x * 64;
    int h  = blockIdx.y;
    int b  = blockIdx.z;
    int bh = b * HEADS + h;
    int t  = threadIdx.x;

    #pragma unroll
    for (int i = 0; i < 16; i++) {
        int e   = t + 256 * i;
        int row = e >> 6;
        int d   = e & 63;
        const float* base = qkv + (size_t)(b * SEQ + st + row) * QKV_N + h * HEAD_D + d;
        size_t o = ((size_t)bh * SEQ + st + row) * HEAD_D + d;
        float q = base[0] * ATTN_SCALE;
        __nv_bfloat16 qhi = __float2bfloat16_rn(q);
        qh[o] = qhi;
        qm[o] = __float2bfloat16_rn(q - __bfloat162float(qhi));
        float k = base[HIDDEN];
        __nv_bfloat16 khi = __float2bfloat16_rn(k);
        kh[o] = khi;
        km[o] = __float2bfloat16_rn(k - __bfloat162float(khi));
        vs[row][d] = base[2 * HIDDEN];
    }
    __syncthreads();
    #pragma unroll
    for (int i = 0; i < 16; i++) {
        int e    = t + 256 * i;
        int drow = e >> 6;
        int scol = e & 63;
        float v = vs[scol][drow];
        __nv_bfloat16 vhi = __float2bfloat16_rn(v);
        size_t o = ((size_t)bh * HEAD_D + drow) * SEQ + st + scol;
        vth[o] = vhi;
        vtm[o] = __float2bfloat16_rn(v - __bfloat162float(vhi));
    }
}

// ---------------------------------------------------------------------------
// mma.sync split-bf16 GEMM (unchanged; at HMMA roofline).
// ---------------------------------------------------------------------------
#define GBM 128
#define GBN 128
#define GBK 32
#define ROWB 80
#define TILE_SZ (128 * ROWB)
#define STAGE_SZ (4 * TILE_SZ)
#define SMEM_MMA (2 * STAGE_SZ)

__device__ __forceinline__ void load_tile_async(uint32_t dst,
                                                const __nv_bfloat16* src,
                                                int row0, int k0, int t)
{
    #pragma unroll
    for (int f = t; f < 512; f += 256) {
        int row = f >> 2, q = f & 3;
        cp16(dst + row * ROWB + q * 16,
             src + (size_t)(row0 + row) * KDIM + k0 + q * 8);
    }
}

__global__ __launch_bounds__(256, 1)
void mma_gemm(const __nv_bfloat16* __restrict__ Ahi,
              const __nv_bfloat16* __restrict__ Amid,
              const __nv_bfloat16* __restrict__ Bhi,
              const __nv_bfloat16* __restrict__ Bmid,
              const float* __restrict__ bias, float* __restrict__ C, int ldN)
{
    extern __shared__ char smraw[];
    uint32_t sb = smem_u32(smraw);

    int t    = threadIdx.x;
    int lane = t & 31;
    int wid  = t >> 5;
    int wm   = wid & 3;
    int wn   = wid >> 2;
    int m0   = blockIdx.y * GBM;
    int n0   = blockIdx.x * GBN;

    int g  = lane >> 3;
    int lr = lane & 7;
    int aRow = ((g & 1) << 3) + lr;
    int aCol = (g >> 1) << 4;
    int bRow = ((g >> 1) << 3) + lr;
    int bCol = (g & 1) << 4;

    float c[2][8][4];
    #pragma unroll
    for (int mi = 0; mi < 2; mi++)
        #pragma unroll
        for (int ng = 0; ng < 8; ng++)
            #pragma unroll
            for (int j = 0; j < 4; j++) c[mi][ng][j] = 0.0f;

    const int NCH = KDIM / GBK;

    {
        uint32_t st = sb;
        load_tile_async(st,               Ahi,  m0, 0, t);
        load_tile_async(st + TILE_SZ,     Amid, m0, 0, t);
        load_tile_async(st + 2 * TILE_SZ, Bhi,  n0, 0, t);
        load_tile_async(st + 3 * TILE_SZ, Bmid, n0, 0, t);
        CP_COMMIT();
    }

    #pragma unroll 1
    for (int i = 0; i < NCH; i++) {
        uint32_t cur = sb + (i & 1) * STAGE_SZ;
        if (i + 1 < NCH) {
            uint32_t nst = sb + ((i + 1) & 1) * STAGE_SZ;
            int k0 = (i + 1) * GBK;
            load_tile_async(nst,               Ahi,  m0, k0, t);
            load_tile_async(nst + TILE_SZ,     Amid, m0, k0, t);
            load_tile_async(nst + 2 * TILE_SZ, Bhi,  n0, k0, t);
            load_tile_async(nst + 3 * TILE_SZ, Bmid, n0, k0, t);
            CP_COMMIT();
            CP_WAIT(1);
        } else {
            CP_WAIT(0);
        }
        __syncthreads();

        uint32_t AhiB = cur;
        uint32_t AmdB = cur + TILE_SZ;
        uint32_t BhiB = cur + 2 * TILE_SZ;
        uint32_t BmdB = cur + 3 * TILE_SZ;

        #pragma unroll
        for (int ks = 0; ks < 2; ks++) {
            int kb = ks * 32;
            uint32_t aH[2][4], aM[2][4], bH[4][4], bM[4][4];

            #pragma unroll
            for (int mi = 0; mi < 2; mi++)
                ldsm4(aH[mi], AhiB + (wm * 32 + mi * 16 + aRow) * ROWB + kb + aCol);
            #pragma unroll
            for (int nb = 0; nb < 4; nb++)
                ldsm4(bH[nb], BhiB + (wn * 64 + nb * 16 + bRow) * ROWB + kb + bCol);
            #pragma unroll
            for (int mi = 0; mi < 2; mi++)
                #pragma unroll
                for (int ng = 0; ng < 8; ng++)
                    mma16816(c[mi][ng], aH[mi], &bH[ng >> 1][(ng & 1) * 2]);

            #pragma unroll
            for (int nb = 0; nb < 4; nb++)
                ldsm4(bM[nb], BmdB + (wn * 64 + nb * 16 + bRow) * ROWB + kb + bCol);
            #pragma unroll
            for (int mi = 0; mi < 2; mi++)
                #pragma unroll
                for (int ng = 0; ng < 8; ng++)
                    mma16816(c[mi][ng], aH[mi], &bM[ng >> 1][(ng & 1) * 2]);

            #pragma unroll
            for (int mi = 0; mi < 2; mi++)
                ldsm4(aM[mi], AmdB + (wm * 32 + mi * 16 + aRow) * ROWB + kb + aCol);
            #pragma unroll
            for (int mi = 0; mi < 2; mi++)
                #pragma unroll
                for (int ng = 0; ng < 8; ng++)
                    mma16816(c[mi][ng], aM[mi], &bH[ng >> 1][(ng & 1) * 2]);
        }
        __syncthreads();
    }

    int r  = lane >> 2;
    int cg = (lane & 3) * 2;
    #pragma unroll
    for (int mi = 0; mi < 2; mi++) {
        #pragma unroll
        for (int ng = 0; ng < 8; ng++) {
            int gn  = n0 + wn * 64 + ng * 8 + cg;
            float2 bb = *(const float2*)(bias + gn);
            int gm  = m0 + wm * 32 + mi * 16 + r;
            float2 o0, o1;
            o0.x = c[mi][ng][0] + bb.x;  o0.y = c[mi][ng][1] + bb.y;
            o1.x = c[mi][ng][2] + bb.x;  o1.y = c[mi][ng][3] + bb.y;
            *(float2*)(C + (size_t)gm * ldN + gn)       = o0;
            *(float2*)(C + (size_t)(gm + 8) * ldN + gn) = o1;
        }
    }
}

// ---------------------------------------------------------------------------
// Tensor-core causal flash attention with sharp-softmax tile skipping.
// ---------------------------------------------------------------------------
#define AP 144
#define AQ_SZ   (128 * AP)
#define AKV_TSZ (64 * AP)
#define AKV_SSZ (4 * AKV_TSZ)
#define SMEM_ATT (2 * AQ_SZ + 2 * AKV_SSZ)

__device__ __forceinline__ void load_kv_tiles(uint32_t dst,
    const __nv_bfloat16* kh, const __nv_bfloat16* km,
    const __nv_bfloat16* vth, const __nv_bfloat16* vtm,
    int bh, int k0, int t)
{
    #pragma unroll
    for (int i = 0; i < 2; i++) {
        int f = t + 256 * i;
        int row = f >> 3, ch = f & 7;
        size_t ko = ((size_t)bh * SEQ + k0 + row) * HEAD_D + ch * 8;
        size_t vo = ((size_t)bh * HEAD_D + row) * SEQ + k0 + ch * 8;
        uint32_t so = row * AP + ch * 16;
        cp16(dst + so,                kh  + ko);
        cp16(dst + AKV_TSZ + so,      km  + ko);
        cp16(dst + 2 * AKV_TSZ + so,  vth + vo);
        cp16(dst + 3 * AKV_TSZ + so,  vtm + vo);
    }
}

__global__ __launch_bounds__(256, 1)
void attn_mma(const __nv_bfloat16* __restrict__ qhp,
              const __nv_bfloat16* __restrict__ qmp,
              const __nv_bfloat16* __restrict__ khp,
              const __nv_bfloat16* __restrict__ kmp,
              const __nv_bfloat16* __restrict__ vthp,
              const __nv_bfloat16* __restrict__ vtmp,
              __nv_bfloat16* __restrict__ ch,
              __nv_bfloat16* __restrict__ cm)
{
    extern __shared__ char smraw[];
    uint32_t sb  = smem_u32(smraw);
    uint32_t QB  = sb;
    uint32_t STG = sb + 2 * AQ_SZ;

    int qt = (int)gridDim.x - 1 - (int)blockIdx.x;
    int h  = blockIdx.y;
    int b  = blockIdx.z;
    int bh = b * HEADS + h;
    int q0 = qt * 128;
    int t    = threadIdx.x;
    int lane = t & 31;
    int wid  = t >> 5;

    int g  = lane >> 3;
    int lr = lane & 7;
    int aRow = ((g & 1) << 3) + lr;
    int aCol = (g >> 1) << 4;
    int bRow = ((g >> 1) << 3) + lr;
    int bCol = (g & 1) << 4;

    {
        const __nv_bfloat16* qsrc[2] = {qhp, qmp};
        #pragma unroll
        for (int a = 0; a < 2; a++) {
            const __nv_bfloat16* p = qsrc[a] + ((size_t)bh * SEQ + q0) * HEAD_D;
            #pragma unroll
            for (int i = 0; i < 4; i++) {
                int f = t + 256 * i;
                int row = f >> 3, chq = f & 7;
                cp16(QB + a * AQ_SZ + row * AP + chq * 16, p + row * HEAD_D + chq * 8);
            }
        }
        CP_COMMIT();
    }
    load_kv_tiles(STG, khp, kmp, vthp, vtmp, bh, 0, t);
    CP_COMMIT();

    CP_WAIT(1);
    __syncthreads();

    uint32_t qfh[4][4], qfm[4][4];
    #pragma unroll
    for (int ks = 0; ks < 4; ks++) {
        ldsm4(qfh[ks], QB +         (wid * 16 + aRow) * AP + ks * 32 + aCol);
        ldsm4(qfm[ks], QB + AQ_SZ + (wid * 16 + aRow) * AP + ks * 32 + aCol);
    }

    float o[8][4];
    #pragma unroll
    for (int nb = 0; nb < 8; nb++)
        #pragma unroll
        for (int j = 0; j < 4; j++) o[nb][j] = 0.0f;
    float m0 = -CUDART_INF_F, m1 = -CUDART_INF_F;
    float l0 = 0.0f, l1 = 0.0f;

    int r0g = q0 + wid * 16 + (lane >> 2);
    const int nkt = qt * 2 + 2;

    #pragma unroll 1
    for (int kt = 0; kt < nkt; kt++) {
        uint32_t cur = STG + (kt & 1) * AKV_SSZ;
        if (kt + 1 < nkt) {
            load_kv_tiles(STG + ((kt + 1) & 1) * AKV_SSZ,
                          khp, kmp, vthp, vtmp, bh, (kt + 1) * 64, t);
            CP_COMMIT();
            CP_WAIT(1);
        } else {
            CP_WAIT(0);
        }
        __syncthreads();

        // ---- pass A: S_hh only ----
        float s[8][4];
        #pragma unroll
        for (int nb = 0; nb < 8; nb++)
            #pragma unroll
            for (int j = 0; j < 4; j++) s[nb][j] = 0.0f;

        #pragma unroll
        for (int ks = 0; ks < 4; ks++) {
            uint32_t bkh[4][4];
            #pragma unroll
            for (int n4 = 0; n4 < 4; n4++)
                ldsm4(bkh[n4], cur + (n4 * 16 + bRow) * AP + ks * 32 + bCol);
            #pragma unroll
            for (int nb = 0; nb < 8; nb++)
                mma16816(s[nb], qfh[ks], &bkh[nb >> 1][(nb & 1) * 2]);
        }

        // ---- causal mask (before skip decision) ----
        if (kt * 64 + 63 > q0 + wid * 16) {
            #pragma unroll
            for (int nb = 0; nb < 8; nb++) {
                int gc = kt * 64 + nb * 8 + (lane & 3) * 2;
                if (gc + 0 > r0g)     s[nb][0] = -CUDART_INF_F;
                if (gc + 1 > r0g)     s[nb][1] = -CUDART_INF_F;
                if (gc + 0 > r0g + 8) s[nb][2] = -CUDART_INF_F;
                if (gc + 1 > r0g + 8) s[nb][3] = -CUDART_INF_F;
            }
        }

        // ---- estimated row max + warp-uniform skip decision ----
        float e0 = -CUDART_INF_F, e1 = -CUDART_INF_F;
        #pragma unroll
        for (int nb = 0; nb < 8; nb++) {
            e0 = fmaxf(e0, fmaxf(s[nb][0], s[nb][1]));
            e1 = fmaxf(e1, fmaxf(s[nb][2], s[nb][3]));
        }
        e0 = fmaxf(e0, __shfl_xor_sync(0xffffffffu, e0, 1));
        e0 = fmaxf(e0, __shfl_xor_sync(0xffffffffu, e0, 2));
        e1 = fmaxf(e1, __shfl_xor_sync(0xffffffffu, e1, 1));
        e1 = fmaxf(e1, __shfl_xor_sync(0xffffffffu, e1, 2));
        bool act = (e0 >= m0 - SKIP_MARGIN) || (e1 >= m1 - SKIP_MARGIN);
        act = __any_sync(0xffffffffu, act);

        if (act) {
            // ---- passes B: add hi*mid + mid*hi corrections ----
            #pragma unroll
            for (int ks = 0; ks < 4; ks++) {
                uint32_t bkh[4][4], bkm[4][4];
                #pragma unroll
                for (int n4 = 0; n4 < 4; n4++)
                    ldsm4(bkh[n4], cur + (n4 * 16 + bRow) * AP + ks * 32 + bCol);
                #pragma unroll
                for (int n4 = 0; n4 < 4; n4++)
                    ldsm4(bkm[n4], cur + AKV_TSZ + (n4 * 16 + bRow) * AP + ks * 32 + bCol);
                #pragma unroll
                for (int nb = 0; nb < 8; nb++) {
                    mma16816(s[nb], qfh[ks], &bkm[nb >> 1][(nb & 1) * 2]);
                    mma16816(s[nb], qfm[ks], &bkh[nb >> 1][(nb & 1) * 2]);
                }
            }

            // ---- online softmax ----
            float tm0 = -CUDART_INF_F, tm1 = -CUDART_INF_F;
            #pragma unroll
            for (int nb = 0; nb < 8; nb++) {
                tm0 = fmaxf(tm0, fmaxf(s[nb][0], s[nb][1]));
                tm1 = fmaxf(tm1, fmaxf(s[nb][2], s[nb][3]));
            }
            tm0 = fmaxf(tm0, __shfl_xor_sync(0xffffffffu, tm0, 1));
            tm0 = fmaxf(tm0, __shfl_xor_sync(0xffffffffu, tm0, 2));
            tm1 = fmaxf(tm1, __shfl_xor_sync(0xffffffffu, tm1, 1));
            tm1 = fmaxf(tm1, __shfl_xor_sync(0xffffffffu, tm1, 2));
            float mn0 = fmaxf(m0, tm0), mn1 = fmaxf(m1, tm1);
            float c0 = __expf(m0 - mn0), c1 = __expf(m1 - mn1);
            m0 = mn0; m1 = mn1;
            float rs0 = 0.0f, rs1 = 0.0f;
            #pragma unroll
            for (int nb = 0; nb < 8; nb++) {
                s[nb][0] = __expf(s[nb][0] - mn0);
                s[nb][1] = __expf(s[nb][1] - mn0);
                s[nb][2] = __expf(s[nb][2] - mn1);
                s[nb][3] = __expf(s[nb][3] - mn1);
                rs0 += s[nb][0] + s[nb][1];
                rs1 += s[nb][2] + s[nb][3];
            }
            l0 = l0 * c0 + rs0;
            l1 = l1 * c1 + rs1;
            #pragma unroll
            for (int nb = 0; nb < 8; nb++) {
                o[nb][0] *= c0; o[nb][1] *= c0;
                o[nb][2] *= c1; o[nb][3] *= c1;
            }

            // ---- O += P V (3-pass, P packed register-direct) ----
            #pragma unroll
            for (int ks = 0; ks < 4; ks++) {
                uint32_t ah[4], am[4];
                split_pk(s[2 * ks][0],     s[2 * ks][1],     ah[0], am[0]);
                split_pk(s[2 * ks][2],     s[2 * ks][3],     ah[1], am[1]);
                split_pk(s[2 * ks + 1][0], s[2 * ks + 1][1], ah[2], am[2]);
                split_pk(s[2 * ks + 1][2], s[2 * ks + 1][3], ah[3], am[3]);

                uint32_t bvh[4][4], bvm[4][4];
                #pragma unroll
                for (int n4 = 0; n4 < 4; n4++)
                    ldsm4(bvh[n4], cur + 2 * AKV_TSZ + (n4 * 16 + bRow) * AP + ks * 32 + bCol);
                #pragma unroll
                for (int n4 = 0; n4 < 4; n4++)
                    ldsm4(bvm[n4], cur + 3 * AKV_TSZ + (n4 * 16 + bRow) * AP + ks * 32 + bCol);
                #pragma unroll
                for (int nb = 0; nb < 8; nb++) {
                    mma16816(o[nb], ah, &bvh[nb >> 1][(nb & 1) * 2]);
                    mma16816(o[nb], ah, &bvm[nb >> 1][(nb & 1) * 2]);
                    mma16816(o[nb], am, &bvh[nb >> 1][(nb & 1) * 2]);
                }
            }
        }
        __syncthreads();
    }

    // ---- finalize: normalize and write ctx as bf16 hi/mid directly ----
    l0 += __shfl_xor_sync(0xffffffffu, l0, 1);
    l0 += __shfl_xor_sync(0xffffffffu, l0, 2);
    l1 += __shfl_xor_sync(0xffffffffu, l1, 1);
    l1 += __shfl_xor_sync(0xffffffffu, l1, 2);
    float inv0 = 1.0f / l0, inv1 = 1.0f / l1;
    int cbase = h * HEAD_D + (lane & 3) * 2;
    #pragma unroll
    for (int nb = 0; nb < 8; nb++) {
        size_t off0 = (size_t)(b * SEQ + r0g) * HIDDEN + cbase + nb * 8;
        size_t off1 = (size_t)(b * SEQ + r0g + 8) * HIDDEN + cbase + nb * 8;
        store_split2(ch, cm, off0, o[nb][0] * inv0, o[nb][1] * inv0);
        store_split2(ch, cm, off1, o[nb][2] * inv1, o[nb][3] * inv1);
    }
}

// ---------------------------------------------------------------------------
extern "C" void kernel_launch(void* const* d_in, const int* in_sizes, int n_in,
                              void* d_out, int out_size)
{
    const float* x     = (const float*)d_in[0];
    const float* W_qkv = (const float*)d_in[1];
    const float* b_qkv = (const float*)d_in[2];
    const float* W_out = (const float*)d_in[3];
    const float* b_out = (const float*)d_in[4];
    float* out = (float*)d_out;

    float *qkv;
    __nv_bfloat16 *x_hi, *x_mid, *c_hi, *c_mid, *wq_hi, *wq_mid, *wo_hi, *wo_mid;
    __nv_bfloat16 *aqh, *aqm, *akh, *akm, *avh, *avm;
    cudaGetSymbolAddress((void**)&qkv,    g_qkv);
    cudaGetSymbolAddress((void**)&x_hi,   g_x_hi);
    cudaGetSymbolAddress((void**)&x_mid,  g_x_mid);
    cudaGetSymbolAddress((void**)&c_hi,   g_c_hi);
    cudaGetSymbolAddress((void**)&c_mid,  g_c_mid);
    cudaGetSymbolAddress((void**)&wq_hi,  g_wq_hi);
    cudaGetSymbolAddress((void**)&wq_mid, g_wq_mid);
    cudaGetSymbolAddress((void**)&wo_hi,  g_wo_hi);
    cudaGetSymbolAddress((void**)&wo_mid, g_wo_mid);
    cudaGetSymbolAddress((void**)&aqh,    g_aq_hi);
    cudaGetSymbolAddress((void**)&aqm,    g_aq_mid);
    cudaGetSymbolAddress((void**)&akh,    g_ak_hi);
    cudaGetSymbolAddress((void**)&akm,    g_ak_mid);
    cudaGetSymbolAddress((void**)&avh,    g_avt_hi);
    cudaGetSymbolAddress((void**)&avm,    g_avt_mid);

    cudaFuncSetAttribute(mma_gemm, cudaFuncAttributeMaxDynamicSharedMemorySize,
                         SMEM_MMA);
    cudaFuncSetAttribute(attn_mma, cudaFuncAttributeMaxDynamicSharedMemorySize,
                         SMEM_ATT);

    // 1) split x -> bf16 hi/mid
    {
        int n4 = M_TOT * HIDDEN / 4;
        split_rows<<<(n4 + 255) / 256, 256>>>((const float4*)x,
                                              (__nv_bfloat162*)x_hi,
                                              (__nv_bfloat162*)x_mid, n4);
    }
    // 2) transpose+split W_qkv
    split_transpose<<<dim3(QKV_N / 32, KDIM / 32), dim3(32, 8)>>>(
        W_qkv, wq_hi, wq_mid, KDIM, QKV_N);
    // 3) QKV projection (tensor cores)
    mma_gemm<<<dim3(QKV_N / GBN, M_TOT / GBM), 256, SMEM_MMA>>>(
        x_hi, x_mid, wq_hi, wq_mid, b_qkv, qkv, QKV_N);
    // 4) prep attention operands
    attn_prep<<<dim3(SEQ / 64, HEADS, BATCH), 256>>>(
        qkv, aqh, aqm, akh, akm, avh, avm);
    // 5) causal attention (tensor cores, tile skipping); writes ctx hi/mid
    attn_mma<<<dim3(SEQ / 128, HEADS, BATCH), 256, SMEM_ATT>>>(
        aqh, aqm, akh, akm, avh, avm, c_hi, c_mid);
    // 6) transpose+split W_out
    split_transpose<<<dim3(HIDDEN / 32, KDIM / 32), dim3(32, 8)>>>(
        W_out, wo_hi, wo_mid, KDIM, HIDDEN);
    // 7) output projection (tensor cores)
    mma_gemm<<<dim3(HIDDEN / GBN, M_TOT / GBM), 256, SMEM_MMA>>>(
        c_hi, c_mid, wo_hi, wo_mid, b_out, out, HIDDEN);
}

// round 13
// speedup vs baseline: 4.1945x; 1.0270x over previous
#include <cuda_runtime.h>
#include <cuda_bf16.h>
#include <math_constants.h>
#include <cstdint>

// Problem constants
#define BATCH   2
#define SEQ     2048
#define HIDDEN  1024
#define HEADS   16
#define HEAD_D  64
#define QKV_N   (3 * HIDDEN)          // 3072
#define M_TOT   (BATCH * SEQ)         // 4096
#define KDIM    1024
#define ATTN_SCALE 125.0f             // TEMP_K / sqrt(HEAD_D)
#define BH_TOT  (BATCH * HEADS)       // 32
#define ATT_ELEMS (BH_TOT * SEQ * HEAD_D)
#define NROWS   (BH_TOT * SEQ)        // 65536
#define CAND_MARGIN 30.0f             // logit-units candidate threshold
#define MAX_CAND 16

// ---------------------------------------------------------------------------
// Scratch (__device__ globals per allocation-free rule)
// ---------------------------------------------------------------------------
__device__ float g_qkv[M_TOT * QKV_N];
__device__ __nv_bfloat16 g_x_hi[M_TOT * HIDDEN];
__device__ __nv_bfloat16 g_x_mid[M_TOT * HIDDEN];
__device__ __nv_bfloat16 g_c_hi[M_TOT * HIDDEN];
__device__ __nv_bfloat16 g_c_mid[M_TOT * HIDDEN];
__device__ __nv_bfloat16 g_wq_hi[QKV_N * KDIM];
__device__ __nv_bfloat16 g_wq_mid[QKV_N * KDIM];
__device__ __nv_bfloat16 g_wo_hi[HIDDEN * KDIM];
__device__ __nv_bfloat16 g_wo_mid[HIDDEN * KDIM];
__device__ __nv_bfloat16 g_aq_hi[ATT_ELEMS];   // [bh][s][64] q*125 bf16-hi
__device__ __nv_bfloat16 g_ak_hi[ATT_ELEMS];   // [bh][s][64] k bf16-hi
__device__ int g_cnt[NROWS];
__device__ int g_cand[NROWS * MAX_CAND];

// ---------------------------------------------------------------------------
__device__ __forceinline__ uint32_t smem_u32(const void* p) {
    uint32_t a;
    asm("{ .reg .u64 t; cvta.to.shared.u64 t, %1; cvt.u32.u64 %0, t; }"
        : "=r"(a) : "l"(p));
    return a;
}

__device__ __forceinline__ void cp16(uint32_t dst, const void* src) {
    asm volatile("cp.async.cg.shared.global [%0], [%1], 16;"
                 :: "r"(dst), "l"(src) : "memory");
}
#define CP_COMMIT() asm volatile("cp.async.commit_group;" ::: "memory")
#define CP_WAIT(n)  asm volatile("cp.async.wait_group %0;" :: "n"(n) : "memory")

__device__ __forceinline__ void ldsm4(uint32_t* r, uint32_t addr) {
    asm volatile("ldmatrix.sync.aligned.m8n8.x4.shared.b16 {%0,%1,%2,%3}, [%4];"
                 : "=r"(r[0]), "=r"(r[1]), "=r"(r[2]), "=r"(r[3]) : "r"(addr));
}

__device__ __forceinline__ void mma16816(float* c, const uint32_t* a,
                                         const uint32_t* b) {
    asm volatile(
        "mma.sync.aligned.m16n8k16.row.col.f32.bf16.bf16.f32 "
        "{%0,%1,%2,%3}, {%4,%5,%6,%7}, {%8,%9}, {%0,%1,%2,%3};"
        : "+f"(c[0]), "+f"(c[1]), "+f"(c[2]), "+f"(c[3])
        : "r"(a[0]), "r"(a[1]), "r"(a[2]), "r"(a[3]), "r"(b[0]), "r"(b[1]));
}

__device__ __forceinline__ void store_split2(__nv_bfloat16* hi,
                                             __nv_bfloat16* mid,
                                             size_t off, float a, float b) {
    __nv_bfloat162 h;
    h.x = __float2bfloat16_rn(a);
    h.y = __float2bfloat16_rn(b);
    *(__nv_bfloat162*)(hi + off) = h;
    __nv_bfloat162 m2 = __floats2bfloat162_rn(a - __bfloat162float(h.x),
                                              b - __bfloat162float(h.y));
    *(__nv_bfloat162*)(mid + off) = m2;
}

// ---------------------------------------------------------------------------
// Prepass 0: zero candidate counters (replaces cudaMemsetAsync).
// ---------------------------------------------------------------------------
__global__ __launch_bounds__(256)
void zero_cnt(int* __restrict__ cnt)
{
    int i = blockIdx.x * 256 + threadIdx.x;
    if (i < NROWS) cnt[i] = 0;
}

// ---------------------------------------------------------------------------
// Prepass 1: elementwise fp32 -> bf16 (hi, mid) split.
// ---------------------------------------------------------------------------
__global__ __launch_bounds__(256)
void split_rows(const float4* __restrict__ src,
                __nv_bfloat162* __restrict__ hi,
                __nv_bfloat162* __restrict__ mid, int n4)
{
    int i = blockIdx.x * blockDim.x + threadIdx.x;
    if (i >= n4) return;
    float4 v = src[i];
    __nv_bfloat16 h0 = __float2bfloat16_rn(v.x);
    __nv_bfloat16 h1 = __float2bfloat16_rn(v.y);
    __nv_bfloat16 h2 = __float2bfloat16_rn(v.z);
    __nv_bfloat16 h3 = __float2bfloat16_rn(v.w);
    __nv_bfloat16 m0 = __float2bfloat16_rn(v.x - __bfloat162float(h0));
    __nv_bfloat16 m1 = __float2bfloat16_rn(v.y - __bfloat162float(h1));
    __nv_bfloat16 m2 = __float2bfloat16_rn(v.z - __bfloat162float(h2));
    __nv_bfloat16 m3 = __float2bfloat16_rn(v.w - __bfloat162float(h3));
    __nv_bfloat162 a, b, c, d;
    a.x = h0; a.y = h1; b.x = h2; b.y = h3;
    c.x = m0; c.y = m1; d.x = m2; d.y = m3;
    hi[2 * i] = a;  hi[2 * i + 1] = b;
    mid[2 * i] = c; mid[2 * i + 1] = d;
}

// ---------------------------------------------------------------------------
// Prepass 2: W [K x N] fp32 -> W^T [N x K] bf16 (hi, mid).
// ---------------------------------------------------------------------------
__global__ __launch_bounds__(256)
void split_transpose(const float* __restrict__ W,
                     __nv_bfloat16* __restrict__ hi,
                     __nv_bfloat16* __restrict__ mid, int K, int N)
{
    __shared__ float s[32][33];
    int n0 = blockIdx.x * 32;
    int k0 = blockIdx.y * 32;
    int tx = threadIdx.x, ty = threadIdx.y;
    #pragma unroll
    for (int i = 0; i < 4; i++) {
        int kk = ty + 8 * i;
        s[kk][tx] = W[(size_t)(k0 + kk) * N + n0 + tx];
    }
    __syncthreads();
    #pragma unroll
    for (int i = 0; i < 4; i++) {
        int nn = ty + 8 * i;
        float v = s[tx][nn];
        __nv_bfloat16 h = __float2bfloat16_rn(v);
        __nv_bfloat16 m = __float2bfloat16_rn(v - __bfloat162float(h));
        size_t o = (size_t)(n0 + nn) * KDIM + k0 + tx;
        hi[o] = h;
        mid[o] = m;
    }
}

// ---------------------------------------------------------------------------
// Prepass 3 (slim): qkv fp32 -> bf16-hi Q (x125) and K only.
// ---------------------------------------------------------------------------
__global__ __launch_bounds__(256)
void attn_prep2(const float* __restrict__ qkv,
                __nv_bfloat16* __restrict__ qh, __nv_bfloat16* __restrict__ kh)
{
    int st = blockIdx.x * 64;
    int h  = blockIdx.y;
    int b  = blockIdx.z;
    int bh = b * HEADS + h;
    int t  = threadIdx.x;
    #pragma unroll
    for (int i = 0; i < 16; i++) {
        int e   = t + 256 * i;       // 0..4095
        int row = e >> 6;
        int d   = e & 63;
        const float* base = qkv + (size_t)(b * SEQ + st + row) * QKV_N + h * HEAD_D + d;
        size_t o = ((size_t)bh * SEQ + st + row) * HEAD_D + d;
        qh[o] = __float2bfloat16_rn(base[0] * ATTN_SCALE);
        kh[o] = __float2bfloat16_rn(base[HIDDEN]);
    }
}

// ---------------------------------------------------------------------------
// mma.sync split-bf16 GEMM (unchanged; at HMMA roofline).
// ---------------------------------------------------------------------------
#define GBM 128
#define GBN 128
#define GBK 32
#define ROWB 80
#define TILE_SZ (128 * ROWB)
#define STAGE_SZ (4 * TILE_SZ)
#define SMEM_MMA (2 * STAGE_SZ)

__device__ __forceinline__ void load_tile_async(uint32_t dst,
                                                const __nv_bfloat16* src,
                                                int row0, int k0, int t)
{
    #pragma unroll
    for (int f = t; f < 512; f += 256) {
        int row = f >> 2, q = f & 3;
        cp16(dst + row * ROWB + q * 16,
             src + (size_t)(row0 + row) * KDIM + k0 + q * 8);
    }
}

__global__ __launch_bounds__(256, 1)
void mma_gemm(const __nv_bfloat16* __restrict__ Ahi,
              const __nv_bfloat16* __restrict__ Amid,
              const __nv_bfloat16* __restrict__ Bhi,
              const __nv_bfloat16* __restrict__ Bmid,
              const float* __restrict__ bias, float* __restrict__ C, int ldN)
{
    extern __shared__ char smraw[];
    uint32_t sb = smem_u32(smraw);

    int t    = threadIdx.x;
    int lane = t & 31;
    int wid  = t >> 5;
    int wm   = wid & 3;
    int wn   = wid >> 2;
    int m0   = blockIdx.y * GBM;
    int n0   = blockIdx.x * GBN;

    int g  = lane >> 3;
    int lr = lane & 7;
    int aRow = ((g & 1) << 3) + lr;
    int aCol = (g >> 1) << 4;
    int bRow = ((g >> 1) << 3) + lr;
    int bCol = (g & 1) << 4;

    float c[2][8][4];
    #pragma unroll
    for (int mi = 0; mi < 2; mi++)
        #pragma unroll
        for (int ng = 0; ng < 8; ng++)
            #pragma unroll
            for (int j = 0; j < 4; j++) c[mi][ng][j] = 0.0f;

    const int NCH = KDIM / GBK;

    {
        uint32_t st = sb;
        load_tile_async(st,               Ahi,  m0, 0, t);
        load_tile_async(st + TILE_SZ,     Amid, m0, 0, t);
        load_tile_async(st + 2 * TILE_SZ, Bhi,  n0, 0, t);
        load_tile_async(st + 3 * TILE_SZ, Bmid, n0, 0, t);
        CP_COMMIT();
    }

    #pragma unroll 1
    for (int i = 0; i < NCH; i++) {
        uint32_t cur = sb + (i & 1) * STAGE_SZ;
        if (i + 1 < NCH) {
            uint32_t nst = sb + ((i + 1) & 1) * STAGE_SZ;
            int k0 = (i + 1) * GBK;
            load_tile_async(nst,               Ahi,  m0, k0, t);
            load_tile_async(nst + TILE_SZ,     Amid, m0, k0, t);
            load_tile_async(nst + 2 * TILE_SZ, Bhi,  n0, k0, t);
            load_tile_async(nst + 3 * TILE_SZ, Bmid, n0, k0, t);
            CP_COMMIT();
            CP_WAIT(1);
        } else {
            CP_WAIT(0);
        }
        __syncthreads();

        uint32_t AhiB = cur;
        uint32_t AmdB = cur + TILE_SZ;
        uint32_t BhiB = cur + 2 * TILE_SZ;
        uint32_t BmdB = cur + 3 * TILE_SZ;

        #pragma unroll
        for (int ks = 0; ks < 2; ks++) {
            int kb = ks * 32;
            uint32_t aH[2][4], aM[2][4], bH[4][4], bM[4][4];

            #pragma unroll
            for (int mi = 0; mi < 2; mi++)
                ldsm4(aH[mi], AhiB + (wm * 32 + mi * 16 + aRow) * ROWB + kb + aCol);
            #pragma unroll
            for (int nb = 0; nb < 4; nb++)
                ldsm4(bH[nb], BhiB + (wn * 64 + nb * 16 + bRow) * ROWB + kb + bCol);
            #pragma unroll
            for (int mi = 0; mi < 2; mi++)
                #pragma unroll
                for (int ng = 0; ng < 8; ng++)
                    mma16816(c[mi][ng], aH[mi], &bH[ng >> 1][(ng & 1) * 2]);

            #pragma unroll
            for (int nb = 0; nb < 4; nb++)
                ldsm4(bM[nb], BmdB + (wn * 64 + nb * 16 + bRow) * ROWB + kb + bCol);
            #pragma unroll
            for (int mi = 0; mi < 2; mi++)
                #pragma unroll
                for (int ng = 0; ng < 8; ng++)
                    mma16816(c[mi][ng], aH[mi], &bM[ng >> 1][(ng & 1) * 2]);

            #pragma unroll
            for (int mi = 0; mi < 2; mi++)
                ldsm4(aM[mi], AmdB + (wm * 32 + mi * 16 + aRow) * ROWB + kb + aCol);
            #pragma unroll
            for (int mi = 0; mi < 2; mi++)
                #pragma unroll
                for (int ng = 0; ng < 8; ng++)
                    mma16816(c[mi][ng], aM[mi], &bH[ng >> 1][(ng & 1) * 2]);
        }
        __syncthreads();
    }

    int r  = lane >> 2;
    int cg = (lane & 3) * 2;
    #pragma unroll
    for (int mi = 0; mi < 2; mi++) {
        #pragma unroll
        for (int ng = 0; ng < 8; ng++) {
            int gn  = n0 + wn * 64 + ng * 8 + cg;
            float2 bb = *(const float2*)(bias + gn);
            int gm  = m0 + wm * 32 + mi * 16 + r;
            float2 o0, o1;
            o0.x = c[mi][ng][0] + bb.x;  o0.y = c[mi][ng][1] + bb.y;
            o1.x = c[mi][ng][2] + bb.x;  o1.y = c[mi][ng][3] + bb.y;
            *(float2*)(C + (size_t)gm * ldN + gn)       = o0;
            *(float2*)(C + (size_t)(gm + 8) * ldN + gn) = o1;
        }
    }
}

// ---------------------------------------------------------------------------
// Attention phase 1: hh-logit scan -> row maxes -> candidate extraction.
// ---------------------------------------------------------------------------
#define AP 144
#define SQ_SZ  (128 * AP)              // 18432 (Q hi)
#define SK_SZ  (64 * AP)               // 9216 per K tile
#define SO_K0   SQ_SZ
#define SO_K1   (SQ_SZ + SK_SZ)
#define SO_TM   (SQ_SZ + 2 * SK_SZ)
#define SO_AF   (SO_TM + 8 * 32 * 2 * 4)
#define SMEM_SCAN (SO_AF + 64)

__device__ __forceinline__ void load_k_tile(uint32_t dst,
    const __nv_bfloat16* kh, int bh, int k0, int t)
{
    #pragma unroll
    for (int i = 0; i < 2; i++) {
        int f = t + 256 * i;
        int row = f >> 3, ch = f & 7;
        cp16(dst + row * AP + ch * 16,
             kh + ((size_t)bh * SEQ + k0 + row) * HEAD_D + ch * 8);
    }
}

__global__ __launch_bounds__(256)
void attn_scan(const __nv_bfloat16* __restrict__ qhp,
               const __nv_bfloat16* __restrict__ khp)
{
    extern __shared__ char smraw[];
    uint32_t sb = smem_u32(smraw);
    float* tmx = (float*)(smraw + SO_TM);
    int*   afl = (int*)(smraw + SO_AF);

    int qt = (int)gridDim.x - 1 - (int)blockIdx.x;
    int h  = blockIdx.y;
    int b  = blockIdx.z;
    int bh = b * HEADS + h;
    int q0 = qt * 128;
    int t    = threadIdx.x;
    int lane = t & 31;
    int wid  = t >> 5;

    int g  = lane >> 3;
    int lr = lane & 7;
    int aRow = ((g & 1) << 3) + lr;
    int aCol = (g >> 1) << 4;
    int bRow = ((g >> 1) << 3) + lr;
    int bCol = (g & 1) << 4;

    // load Q hi
    {
        const __nv_bfloat16* p = qhp + ((size_t)bh * SEQ + q0) * HEAD_D;
        #pragma unroll
        for (int i = 0; i < 4; i++) {
            int f = t + 256 * i;
            int row = f >> 3, chq = f & 7;
            cp16(sb + row * AP + chq * 16, p + row * HEAD_D + chq * 8);
        }
        CP_COMMIT();
    }
    load_k_tile(sb + SO_K0, khp, bh, 0, t);
    CP_COMMIT();
    CP_WAIT(1);
    __syncthreads();

    uint32_t qfh[4][4];
    #pragma unroll
    for (int ks = 0; ks < 4; ks++)
        ldsm4(qfh[ks], sb + (wid * 16 + aRow) * AP + ks * 32 + aCol);

    float m0 = -CUDART_INF_F, m1 = -CUDART_INF_F;   // per-row running max
    int r0g = q0 + wid * 16 + (lane >> 2);
    int rtop = q0 + wid * 16 + 15;                  // warp's last row
    const int nkt = qt * 2 + 2;

    // ---- 1a: scan, record row maxes + tile group maxes ----
    #pragma unroll 1
    for (int kt = 0; kt < nkt; kt++) {
        uint32_t cur = sb + ((kt & 1) ? SO_K1 : SO_K0);
        if (kt + 1 < nkt) {
            load_k_tile(sb + (((kt + 1) & 1) ? SO_K1 : SO_K0), khp, bh,
                        (kt + 1) * 64, t);
            CP_COMMIT();
            CP_WAIT(1);
        } else {
            CP_WAIT(0);
        }
        __syncthreads();

        float gm0 = -CUDART_INF_F, gm1 = -CUDART_INF_F;
        if (kt * 64 <= rtop) {           // warp-uniform: not fully masked
            float s[8][4];
            #pragma unroll
            for (int nb = 0; nb < 8; nb++)
                #pragma unroll
                for (int j = 0; j < 4; j++) s[nb][j] = 0.0f;
            #pragma unroll
            for (int ks = 0; ks < 4; ks++) {
                uint32_t bk[4][4];
                #pragma unroll
                for (int n4 = 0; n4 < 4; n4++)
                    ldsm4(bk[n4], cur + (n4 * 16 + bRow) * AP + ks * 32 + bCol);
                #pragma unroll
                for (int nb = 0; nb < 8; nb++)
                    mma16816(s[nb], qfh[ks], &bk[nb >> 1][(nb & 1) * 2]);
            }
            if (kt * 64 + 63 > q0 + wid * 16) {
                #pragma unroll
                for (int nb = 0; nb < 8; nb++) {
                    int gc = kt * 64 + nb * 8 + (lane & 3) * 2;
                    if (gc + 0 > r0g)     s[nb][0] = -CUDART_INF_F;
                    if (gc + 1 > r0g)     s[nb][1] = -CUDART_INF_F;
                    if (gc + 0 > r0g + 8) s[nb][2] = -CUDART_INF_F;
                    if (gc + 1 > r0g + 8) s[nb][3] = -CUDART_INF_F;
                }
            }
            float tm0 = -CUDART_INF_F, tm1 = -CUDART_INF_F;
            #pragma unroll
            for (int nb = 0; nb < 8; nb++) {
                tm0 = fmaxf(tm0, fmaxf(s[nb][0], s[nb][1]));
                tm1 = fmaxf(tm1, fmaxf(s[nb][2], s[nb][3]));
            }
            tm0 = fmaxf(tm0, __shfl_xor_sync(0xffffffffu, tm0, 1));
            tm0 = fmaxf(tm0, __shfl_xor_sync(0xffffffffu, tm0, 2));
            tm1 = fmaxf(tm1, __shfl_xor_sync(0xffffffffu, tm1, 1));
            tm1 = fmaxf(tm1, __shfl_xor_sync(0xffffffffu, tm1, 2));
            m0 = fmaxf(m0, tm0);
            m1 = fmaxf(m1, tm1);
            gm0 = tm0; gm1 = tm1;
            gm0 = fmaxf(gm0, __shfl_xor_sync(0xffffffffu, gm0, 4));
            gm0 = fmaxf(gm0, __shfl_xor_sync(0xffffffffu, gm0, 8));
            gm0 = fmaxf(gm0, __shfl_xor_sync(0xffffffffu, gm0, 16));
            gm1 = fmaxf(gm1, __shfl_xor_sync(0xffffffffu, gm1, 4));
            gm1 = fmaxf(gm1, __shfl_xor_sync(0xffffffffu, gm1, 8));
            gm1 = fmaxf(gm1, __shfl_xor_sync(0xffffffffu, gm1, 16));
        }
        if (lane == 0) {
            tmx[(wid * 32 + kt) * 2 + 0] = gm0;
            tmx[(wid * 32 + kt) * 2 + 1] = gm1;
        }
        __syncthreads();
    }

    // warp-min of row maxes (for tile pruning)
    float wmin = fminf(m0, m1);
    wmin = fminf(wmin, __shfl_xor_sync(0xffffffffu, wmin, 4));
    wmin = fminf(wmin, __shfl_xor_sync(0xffffffffu, wmin, 8));
    wmin = fminf(wmin, __shfl_xor_sync(0xffffffffu, wmin, 16));
    float thr = wmin - (CAND_MARGIN + 1.0f);

    // ---- 1b: revisit candidate tiles ----
    #pragma unroll 1
    for (int kt = 0; kt < nkt; kt++) {
        bool wact = (tmx[(wid * 32 + kt) * 2 + 0] >= thr) ||
                    (tmx[(wid * 32 + kt) * 2 + 1] >= thr);
        if (lane == 0) afl[(kt & 1) * 8 + wid] = wact ? 1 : 0;
        __syncthreads();
        int any = 0;
        #pragma unroll
        for (int w = 0; w < 8; w++) any |= afl[(kt & 1) * 8 + w];
        if (!any) continue;              // CTA-uniform skip

        load_k_tile(sb + SO_K0, khp, bh, kt * 64, t);
        CP_COMMIT();
        CP_WAIT(0);
        __syncthreads();

        if (wact && kt * 64 <= rtop) {
            float s[8][4];
            #pragma unroll
            for (int nb = 0; nb < 8; nb++)
                #pragma unroll
                for (int j = 0; j < 4; j++) s[nb][j] = 0.0f;
            #pragma unroll
            for (int ks = 0; ks < 4; ks++) {
                uint32_t bk[4][4];
                #pragma unroll
                for (int n4 = 0; n4 < 4; n4++)
                    ldsm4(bk[n4], sb + SO_K0 + (n4 * 16 + bRow) * AP + ks * 32 + bCol);
                #pragma unroll
                for (int nb = 0; nb < 8; nb++)
                    mma16816(s[nb], qfh[ks], &bk[nb >> 1][(nb & 1) * 2]);
            }
            if (kt * 64 + 63 > q0 + wid * 16) {
                #pragma unroll
                for (int nb = 0; nb < 8; nb++) {
                    int gc = kt * 64 + nb * 8 + (lane & 3) * 2;
                    if (gc + 0 > r0g)     s[nb][0] = -CUDART_INF_F;
                    if (gc + 1 > r0g)     s[nb][1] = -CUDART_INF_F;
                    if (gc + 0 > r0g + 8) s[nb][2] = -CUDART_INF_F;
                    if (gc + 1 > r0g + 8) s[nb][3] = -CUDART_INF_F;
                }
            }
            int grow0 = bh * SEQ + r0g;
            int grow1 = grow0 + 8;
            float th0 = m0 - CAND_MARGIN;
            float th1 = m1 - CAND_MARGIN;
            #pragma unroll
            for (int nb = 0; nb < 8; nb++) {
                int kbase = kt * 64 + nb * 8 + (lane & 3) * 2;
                if (s[nb][0] >= th0) {
                    int idx = atomicAdd(&g_cnt[grow0], 1);
                    if (idx < MAX_CAND) g_cand[grow0 * MAX_CAND + idx] = kbase;
                }
                if (s[nb][1] >= th0) {
                    int idx = atomicAdd(&g_cnt[grow0], 1);
                    if (idx < MAX_CAND) g_cand[grow0 * MAX_CAND + idx] = kbase + 1;
                }
                if (s[nb][2] >= th1) {
                    int idx = atomicAdd(&g_cnt[grow1], 1);
                    if (idx < MAX_CAND) g_cand[grow1 * MAX_CAND + idx] = kbase;
                }
                if (s[nb][3] >= th1) {
                    int idx = atomicAdd(&g_cnt[grow1], 1);
                    if (idx < MAX_CAND) g_cand[grow1 * MAX_CAND + idx] = kbase + 1;
                }
            }
        }
        __syncthreads();
    }
}

// ---------------------------------------------------------------------------
// Attention phase 2: exact fp32 softmax over candidates.
// One warp per query row; <=16 candidates; writes ctx as bf16 hi/mid.
// ---------------------------------------------------------------------------
__global__ __launch_bounds__(256)
void attn_gather(const float* __restrict__ qkv,
                 __nv_bfloat16* __restrict__ ch,
                 __nv_bfloat16* __restrict__ cm)
{
    int w    = (blockIdx.x * 256 + threadIdx.x) >> 5;   // global row
    int lane = threadIdx.x & 31;
    int bh = w >> 11;            // / SEQ
    int sq = w & (SEQ - 1);
    int b  = bh >> 4;
    int h  = bh & 15;

    const float* qb = qkv + ((size_t)(b * SEQ + sq)) * QKV_N + h * HEAD_D;
    float q0 = qb[lane * 2]     * ATTN_SCALE;
    float q1 = qb[lane * 2 + 1] * ATTN_SCALE;

    int cnt = g_cnt[w];
    if (cnt > MAX_CAND) cnt = MAX_CAND;

    size_t off = (size_t)(b * SEQ + sq) * HIDDEN + h * HEAD_D + lane * 2;
    if (cnt <= 0) {              // defensive (argmax key always present)
        store_split2(ch, cm, off, 0.0f, 0.0f);
        return;
    }

    // load + sort candidate indices (determinism; insertion sort, n<=16)
    int cd[MAX_CAND];
    #pragma unroll
    for (int i = 0; i < MAX_CAND; i++)
        cd[i] = (i < cnt) ? g_cand[w * MAX_CAND + i] : 0x7fffffff;
    #pragma unroll
    for (int i = 1; i < MAX_CAND; i++) {
        int key = cd[i];
        #pragma unroll
        for (int j = i - 1; j >= 0; j--) {
            if (cd[j] > key) { cd[j + 1] = cd[j]; cd[j] = key; key = cd[j]; }
        }
    }

    // exact logits
    float sv[MAX_CAND];
    #pragma unroll
    for (int i = 0; i < MAX_CAND; i++) {
        float p = -CUDART_INF_F;
        if (i < cnt) {
            const float* kb = qkv + ((size_t)(b * SEQ + cd[i])) * QKV_N
                            + HIDDEN + h * HEAD_D;
            p = q0 * kb[lane * 2] + q1 * kb[lane * 2 + 1];
            p += __shfl_xor_sync(0xffffffffu, p, 16);
            p += __shfl_xor_sync(0xffffffffu, p, 8);
            p += __shfl_xor_sync(0xffffffffu, p, 4);
            p += __shfl_xor_sync(0xffffffffu, p, 2);
            p += __shfl_xor_sync(0xffffffffu, p, 1);
        }
        sv[i] = p;
    }

    float mx = -CUDART_INF_F;
    #pragma unroll
    for (int i = 0; i < MAX_CAND; i++) mx = fmaxf(mx, sv[i]);

    float l = 0.0f, o0 = 0.0f, o1 = 0.0f;
    #pragma unroll
    for (int i = 0; i < MAX_CAND; i++) {
        if (i < cnt) {
            float pe = __expf(sv[i] - mx);
            l += pe;
            const float* vb = qkv + ((size_t)(b * SEQ + cd[i])) * QKV_N
                            + 2 * HIDDEN + h * HEAD_D;
            o0 += pe * vb[lane * 2];
            o1 += pe * vb[lane * 2 + 1];
        }
    }
    float inv = 1.0f / l;
    store_split2(ch, cm, off, o0 * inv, o1 * inv);
}

// ---------------------------------------------------------------------------
extern "C" void kernel_launch(void* const* d_in, const int* in_sizes, int n_in,
                              void* d_out, int out_size)
{
    const float* x     = (const float*)d_in[0];
    const float* W_qkv = (const float*)d_in[1];
    const float* b_qkv = (const float*)d_in[2];
    const float* W_out = (const float*)d_in[3];
    const float* b_out = (const float*)d_in[4];
    float* out = (float*)d_out;

    float *qkv;
    __nv_bfloat16 *x_hi, *x_mid, *c_hi, *c_mid, *wq_hi, *wq_mid, *wo_hi, *wo_mid;
    __nv_bfloat16 *aqh, *akh;
    int* cnt_ptr;
    cudaGetSymbolAddress((void**)&qkv,    g_qkv);
    cudaGetSymbolAddress((void**)&x_hi,   g_x_hi);
    cudaGetSymbolAddress((void**)&x_mid,  g_x_mid);
    cudaGetSymbolAddress((void**)&c_hi,   g_c_hi);
    cudaGetSymbolAddress((void**)&c_mid,  g_c_mid);
    cudaGetSymbolAddress((void**)&wq_hi,  g_wq_hi);
    cudaGetSymbolAddress((void**)&wq_mid, g_wq_mid);
    cudaGetSymbolAddress((void**)&wo_hi,  g_wo_hi);
    cudaGetSymbolAddress((void**)&wo_mid, g_wo_mid);
    cudaGetSymbolAddress((void**)&aqh,    g_aq_hi);
    cudaGetSymbolAddress((void**)&akh,    g_ak_hi);
    cudaGetSymbolAddress((void**)&cnt_ptr, g_cnt);

    cudaFuncSetAttribute(mma_gemm, cudaFuncAttributeMaxDynamicSharedMemorySize,
                         SMEM_MMA);
    cudaFuncSetAttribute(attn_scan, cudaFuncAttributeMaxDynamicSharedMemorySize,
                         SMEM_SCAN);

    // 0) zero candidate counters (plain kernel; no memset API in capture)
    zero_cnt<<<(NROWS + 255) / 256, 256>>>(cnt_ptr);
    // 1) split x -> bf16 hi/mid
    {
        int n4 = M_TOT * HIDDEN / 4;
        split_rows<<<(n4 + 255) / 256, 256>>>((const float4*)x,
                                              (__nv_bfloat162*)x_hi,
                                              (__nv_bfloat162*)x_mid, n4);
    }
    // 2) transpose+split W_qkv
    split_transpose<<<dim3(QKV_N / 32, KDIM / 32), dim3(32, 8)>>>(
        W_qkv, wq_hi, wq_mid, KDIM, QKV_N);
    // 3) QKV projection (tensor cores)
    mma_gemm<<<dim3(QKV_N / GBN, M_TOT / GBM), 256, SMEM_MMA>>>(
        x_hi, x_mid, wq_hi, wq_mid, b_qkv, qkv, QKV_N);
    // 4) prep bf16-hi Q/K
    attn_prep2<<<dim3(SEQ / 64, HEADS, BATCH), 256>>>(qkv, aqh, akh);
    // 5) phase 1: scan + candidate extraction
    attn_scan<<<dim3(SEQ / 128, HEADS, BATCH), 256, SMEM_SCAN>>>(aqh, akh);
    // 6) phase 2: exact softmax over candidates -> ctx hi/mid
    attn_gather<<<NROWS / 8, 256>>>(qkv, c_hi, c_mid);
    // 7) transpose+split W_out
    split_transpose<<<dim3(HIDDEN / 32, KDIM / 32), dim3(32, 8)>>>(
        W_out, wo_hi, wo_mid, KDIM, HIDDEN);
    // 8) output projection (tensor cores)
    mma_gemm<<<dim3(HIDDEN / GBN, M_TOT / GBM), 256, SMEM_MMA>>>(
        c_hi, c_mid, wo_hi, wo_mid, b_out, out, HIDDEN);
}

// round 14
// speedup vs baseline: 4.6576x; 1.1104x over previous
#include <cuda_runtime.h>
#include <cuda_bf16.h>
#include <math_constants.h>
#include <cstdint>

// Problem constants
#define BATCH   2
#define SEQ     2048
#define HIDDEN  1024
#define HEADS   16
#define HEAD_D  64
#define QKV_N   (3 * HIDDEN)          // 3072
#define M_TOT   (BATCH * SEQ)         // 4096
#define KDIM    1024
#define ATTN_SCALE 125.0f             // TEMP_K / sqrt(HEAD_D)
#define BH_TOT  (BATCH * HEADS)       // 32
#define ATT_ELEMS (BH_TOT * SEQ * HEAD_D)
#define NROWS   (BH_TOT * SEQ)        // 65536
#define CAND_MARGIN 30.0f             // logit-units candidate threshold
#define MAX_CAND 16

// ---------------------------------------------------------------------------
// Scratch (__device__ globals per allocation-free rule)
// ---------------------------------------------------------------------------
__device__ float g_qkv[M_TOT * QKV_N];
__device__ __nv_bfloat16 g_x_hi[M_TOT * HIDDEN];
__device__ __nv_bfloat16 g_x_mid[M_TOT * HIDDEN];
__device__ __nv_bfloat16 g_c_hi[M_TOT * HIDDEN];
__device__ __nv_bfloat16 g_c_mid[M_TOT * HIDDEN];
__device__ __nv_bfloat16 g_wq_hi[QKV_N * KDIM];
__device__ __nv_bfloat16 g_wq_mid[QKV_N * KDIM];
__device__ __nv_bfloat16 g_wo_hi[HIDDEN * KDIM];
__device__ __nv_bfloat16 g_wo_mid[HIDDEN * KDIM];
__device__ __nv_bfloat16 g_aq_hi[ATT_ELEMS];   // [bh][s][64] q*125 bf16-hi
__device__ __nv_bfloat16 g_ak_hi[ATT_ELEMS];   // [bh][s][64] k bf16-hi
__device__ int g_cnt[NROWS];
__device__ int g_cand[NROWS * MAX_CAND];

// ---------------------------------------------------------------------------
__device__ __forceinline__ uint32_t smem_u32(const void* p) {
    uint32_t a;
    asm("{ .reg .u64 t; cvta.to.shared.u64 t, %1; cvt.u32.u64 %0, t; }"
        : "=r"(a) : "l"(p));
    return a;
}

__device__ __forceinline__ void cp16(uint32_t dst, const void* src) {
    asm volatile("cp.async.cg.shared.global [%0], [%1], 16;"
                 :: "r"(dst), "l"(src) : "memory");
}
#define CP_COMMIT() asm volatile("cp.async.commit_group;" ::: "memory")
#define CP_WAIT(n)  asm volatile("cp.async.wait_group %0;" :: "n"(n) : "memory")

__device__ __forceinline__ void ldsm4(uint32_t* r, uint32_t addr) {
    asm volatile("ldmatrix.sync.aligned.m8n8.x4.shared.b16 {%0,%1,%2,%3}, [%4];"
                 : "=r"(r[0]), "=r"(r[1]), "=r"(r[2]), "=r"(r[3]) : "r"(addr));
}

__device__ __forceinline__ void mma16816(float* c, const uint32_t* a,
                                         const uint32_t* b) {
    asm volatile(
        "mma.sync.aligned.m16n8k16.row.col.f32.bf16.bf16.f32 "
        "{%0,%1,%2,%3}, {%4,%5,%6,%7}, {%8,%9}, {%0,%1,%2,%3};"
        : "+f"(c[0]), "+f"(c[1]), "+f"(c[2]), "+f"(c[3])
        : "r"(a[0]), "r"(a[1]), "r"(a[2]), "r"(a[3]), "r"(b[0]), "r"(b[1]));
}

__device__ __forceinline__ void store_split2(__nv_bfloat16* hi,
                                             __nv_bfloat16* mid,
                                             size_t off, float a, float b) {
    __nv_bfloat162 h;
    h.x = __float2bfloat16_rn(a);
    h.y = __float2bfloat16_rn(b);
    *(__nv_bfloat162*)(hi + off) = h;
    __nv_bfloat162 m2 = __floats2bfloat162_rn(a - __bfloat162float(h.x),
                                              b - __bfloat162float(h.y));
    *(__nv_bfloat162*)(mid + off) = m2;
}

// ---------------------------------------------------------------------------
// Prepass 0: zero candidate counters.
// ---------------------------------------------------------------------------
__global__ __launch_bounds__(256)
void zero_cnt(int* __restrict__ cnt)
{
    int i = blockIdx.x * 256 + threadIdx.x;
    if (i < NROWS) cnt[i] = 0;
}

// ---------------------------------------------------------------------------
// Prepass 1: elementwise fp32 -> bf16 (hi, mid) split.
// ---------------------------------------------------------------------------
__global__ __launch_bounds__(256)
void split_rows(const float4* __restrict__ src,
                __nv_bfloat162* __restrict__ hi,
                __nv_bfloat162* __restrict__ mid, int n4)
{
    int i = blockIdx.x * blockDim.x + threadIdx.x;
    if (i >= n4) return;
    float4 v = src[i];
    __nv_bfloat16 h0 = __float2bfloat16_rn(v.x);
    __nv_bfloat16 h1 = __float2bfloat16_rn(v.y);
    __nv_bfloat16 h2 = __float2bfloat16_rn(v.z);
    __nv_bfloat16 h3 = __float2bfloat16_rn(v.w);
    __nv_bfloat16 m0 = __float2bfloat16_rn(v.x - __bfloat162float(h0));
    __nv_bfloat16 m1 = __float2bfloat16_rn(v.y - __bfloat162float(h1));
    __nv_bfloat16 m2 = __float2bfloat16_rn(v.z - __bfloat162float(h2));
    __nv_bfloat16 m3 = __float2bfloat16_rn(v.w - __bfloat162float(h3));
    __nv_bfloat162 a, b, c, d;
    a.x = h0; a.y = h1; b.x = h2; b.y = h3;
    c.x = m0; c.y = m1; d.x = m2; d.y = m3;
    hi[2 * i] = a;  hi[2 * i + 1] = b;
    mid[2 * i] = c; mid[2 * i + 1] = d;
}

// ---------------------------------------------------------------------------
// Prepass 2: W [K x N] fp32 -> W^T [N x K] bf16 (hi, mid).
// ---------------------------------------------------------------------------
__global__ __launch_bounds__(256)
void split_transpose(const float* __restrict__ W,
                     __nv_bfloat16* __restrict__ hi,
                     __nv_bfloat16* __restrict__ mid, int K, int N)
{
    __shared__ float s[32][33];
    int n0 = blockIdx.x * 32;
    int k0 = blockIdx.y * 32;
    int tx = threadIdx.x, ty = threadIdx.y;
    #pragma unroll
    for (int i = 0; i < 4; i++) {
        int kk = ty + 8 * i;
        s[kk][tx] = W[(size_t)(k0 + kk) * N + n0 + tx];
    }
    __syncthreads();
    #pragma unroll
    for (int i = 0; i < 4; i++) {
        int nn = ty + 8 * i;
        float v = s[tx][nn];
        __nv_bfloat16 h = __float2bfloat16_rn(v);
        __nv_bfloat16 m = __float2bfloat16_rn(v - __bfloat162float(h));
        size_t o = (size_t)(n0 + nn) * KDIM + k0 + tx;
        hi[o] = h;
        mid[o] = m;
    }
}

// ---------------------------------------------------------------------------
// Prepass 3 (slim): qkv fp32 -> bf16-hi Q (x125) and K only.
// ---------------------------------------------------------------------------
__global__ __launch_bounds__(256)
void attn_prep2(const float* __restrict__ qkv,
                __nv_bfloat16* __restrict__ qh, __nv_bfloat16* __restrict__ kh)
{
    int st = blockIdx.x * 64;
    int h  = blockIdx.y;
    int b  = blockIdx.z;
    int bh = b * HEADS + h;
    int t  = threadIdx.x;
    #pragma unroll
    for (int i = 0; i < 16; i++) {
        int e   = t + 256 * i;       // 0..4095
        int row = e >> 6;
        int d   = e & 63;
        const float* base = qkv + (size_t)(b * SEQ + st + row) * QKV_N + h * HEAD_D + d;
        size_t o = ((size_t)bh * SEQ + st + row) * HEAD_D + d;
        qh[o] = __float2bfloat16_rn(base[0] * ATTN_SCALE);
        kh[o] = __float2bfloat16_rn(base[HIDDEN]);
    }
}

// ---------------------------------------------------------------------------
// mma.sync split-bf16 GEMM, v2: 2 CTAs/SM.
// B-fragments processed in two 32-col halves so only 16 B-frag regs are live
// -> ~121 regs, fits __launch_bounds__(256, 2). Doubled occupancy hides
// ldsm/HMMA latency and the per-chunk sync bubble.
// ---------------------------------------------------------------------------
#define GBM 128
#define GBN 128
#define GBK 32
#define ROWB 80
#define TILE_SZ (128 * ROWB)
#define STAGE_SZ (4 * TILE_SZ)
#define SMEM_MMA (2 * STAGE_SZ)

__device__ __forceinline__ void load_tile_async(uint32_t dst,
                                                const __nv_bfloat16* src,
                                                int row0, int k0, int t)
{
    #pragma unroll
    for (int f = t; f < 512; f += 256) {
        int row = f >> 2, q = f & 3;
        cp16(dst + row * ROWB + q * 16,
             src + (size_t)(row0 + row) * KDIM + k0 + q * 8);
    }
}

__global__ __launch_bounds__(256, 2)
void mma_gemm(const __nv_bfloat16* __restrict__ Ahi,
              const __nv_bfloat16* __restrict__ Amid,
              const __nv_bfloat16* __restrict__ Bhi,
              const __nv_bfloat16* __restrict__ Bmid,
              const float* __restrict__ bias, float* __restrict__ C, int ldN)
{
    extern __shared__ char smraw[];
    uint32_t sb = smem_u32(smraw);

    int t    = threadIdx.x;
    int lane = t & 31;
    int wid  = t >> 5;
    int wm   = wid & 3;
    int wn   = wid >> 2;
    int m0   = blockIdx.y * GBM;
    int n0   = blockIdx.x * GBN;

    int g  = lane >> 3;
    int lr = lane & 7;
    int aRow = ((g & 1) << 3) + lr;
    int aCol = (g >> 1) << 4;
    int bRow = ((g >> 1) << 3) + lr;
    int bCol = (g & 1) << 4;

    float c[2][8][4];
    #pragma unroll
    for (int mi = 0; mi < 2; mi++)
        #pragma unroll
        for (int ng = 0; ng < 8; ng++)
            #pragma unroll
            for (int j = 0; j < 4; j++) c[mi][ng][j] = 0.0f;

    const int NCH = KDIM / GBK;

    {
        uint32_t st = sb;
        load_tile_async(st,               Ahi,  m0, 0, t);
        load_tile_async(st + TILE_SZ,     Amid, m0, 0, t);
        load_tile_async(st + 2 * TILE_SZ, Bhi,  n0, 0, t);
        load_tile_async(st + 3 * TILE_SZ, Bmid, n0, 0, t);
        CP_COMMIT();
    }

    #pragma unroll 1
    for (int i = 0; i < NCH; i++) {
        uint32_t cur = sb + (i & 1) * STAGE_SZ;
        if (i + 1 < NCH) {
            uint32_t nst = sb + ((i + 1) & 1) * STAGE_SZ;
            int k0 = (i + 1) * GBK;
            load_tile_async(nst,               Ahi,  m0, k0, t);
            load_tile_async(nst + TILE_SZ,     Amid, m0, k0, t);
            load_tile_async(nst + 2 * TILE_SZ, Bhi,  n0, k0, t);
            load_tile_async(nst + 3 * TILE_SZ, Bmid, n0, k0, t);
            CP_COMMIT();
            CP_WAIT(1);
        } else {
            CP_WAIT(0);
        }
        __syncthreads();

        uint32_t AhiB = cur;
        uint32_t AmdB = cur + TILE_SZ;
        uint32_t BhiB = cur + 2 * TILE_SZ;
        uint32_t BmdB = cur + 3 * TILE_SZ;

        #pragma unroll
        for (int ks = 0; ks < 2; ks++) {
            int kb = ks * 32;
            uint32_t aH[2][4], aM[2][4];
            #pragma unroll
            for (int mi = 0; mi < 2; mi++)
                ldsm4(aH[mi], AhiB + (wm * 32 + mi * 16 + aRow) * ROWB + kb + aCol);
            #pragma unroll
            for (int mi = 0; mi < 2; mi++)
                ldsm4(aM[mi], AmdB + (wm * 32 + mi * 16 + aRow) * ROWB + kb + aCol);

            #pragma unroll
            for (int nh = 0; nh < 2; nh++) {
                uint32_t bH[2][4], bM[2][4];
                #pragma unroll
                for (int nb = 0; nb < 2; nb++)
                    ldsm4(bH[nb], BhiB + (wn * 64 + nh * 32 + nb * 16 + bRow) * ROWB + kb + bCol);
                #pragma unroll
                for (int nb = 0; nb < 2; nb++)
                    ldsm4(bM[nb], BmdB + (wn * 64 + nh * 32 + nb * 16 + bRow) * ROWB + kb + bCol);

                // pass 1: hi*hi (8 independent accumulator chains)
                #pragma unroll
                for (int mi = 0; mi < 2; mi++)
                    #pragma unroll
                    for (int ng = 0; ng < 4; ng++)
                        mma16816(c[mi][nh * 4 + ng], aH[mi],
                                 &bH[ng >> 1][(ng & 1) * 2]);
                // pass 2: hi*mid
                #pragma unroll
                for (int mi = 0; mi < 2; mi++)
                    #pragma unroll
                    for (int ng = 0; ng < 4; ng++)
                        mma16816(c[mi][nh * 4 + ng], aH[mi],
                                 &bM[ng >> 1][(ng & 1) * 2]);
                // pass 3: mid*hi
                #pragma unroll
                for (int mi = 0; mi < 2; mi++)
                    #pragma unroll
                    for (int ng = 0; ng < 4; ng++)
                        mma16816(c[mi][nh * 4 + ng], aM[mi],
                                 &bH[ng >> 1][(ng & 1) * 2]);
            }
        }
        __syncthreads();
    }

    int r  = lane >> 2;
    int cg = (lane & 3) * 2;
    #pragma unroll
    for (int mi = 0; mi < 2; mi++) {
        #pragma unroll
        for (int ng = 0; ng < 8; ng++) {
            int gn  = n0 + wn * 64 + ng * 8 + cg;
            float2 bb = *(const float2*)(bias + gn);
            int gm  = m0 + wm * 32 + mi * 16 + r;
            float2 o0, o1;
            o0.x = c[mi][ng][0] + bb.x;  o0.y = c[mi][ng][1] + bb.y;
            o1.x = c[mi][ng][2] + bb.x;  o1.y = c[mi][ng][3] + bb.y;
            *(float2*)(C + (size_t)gm * ldN + gn)       = o0;
            *(float2*)(C + (size_t)(gm + 8) * ldN + gn) = o1;
        }
    }
}

// ---------------------------------------------------------------------------
// Attention phase 1: hh-logit scan -> row maxes -> candidate extraction.
// ---------------------------------------------------------------------------
#define AP 144
#define SQ_SZ  (128 * AP)              // 18432 (Q hi)
#define SK_SZ  (64 * AP)               // 9216 per K tile
#define SO_K0   SQ_SZ
#define SO_K1   (SQ_SZ + SK_SZ)
#define SO_TM   (SQ_SZ + 2 * SK_SZ)
#define SO_AF   (SO_TM + 8 * 32 * 2 * 4)
#define SMEM_SCAN (SO_AF + 64)

__device__ __forceinline__ void load_k_tile(uint32_t dst,
    const __nv_bfloat16* kh, int bh, int k0, int t)
{
    #pragma unroll
    for (int i = 0; i < 2; i++) {
        int f = t + 256 * i;
        int row = f >> 3, ch = f & 7;
        cp16(dst + row * AP + ch * 16,
             kh + ((size_t)bh * SEQ + k0 + row) * HEAD_D + ch * 8);
    }
}

__global__ __launch_bounds__(256)
void attn_scan(const __nv_bfloat16* __restrict__ qhp,
               const __nv_bfloat16* __restrict__ khp)
{
    extern __shared__ char smraw[];
    uint32_t sb = smem_u32(smraw);
    float* tmx = (float*)(smraw + SO_TM);
    int*   afl = (int*)(smraw + SO_AF);

    int qt = (int)gridDim.x - 1 - (int)blockIdx.x;
    int h  = blockIdx.y;
    int b  = blockIdx.z;
    int bh = b * HEADS + h;
    int q0 = qt * 128;
    int t    = threadIdx.x;
    int lane = t & 31;
    int wid  = t >> 5;

    int g  = lane >> 3;
    int lr = lane & 7;
    int aRow = ((g & 1) << 3) + lr;
    int aCol = (g >> 1) << 4;
    int bRow = ((g >> 1) << 3) + lr;
    int bCol = (g & 1) << 4;

    // load Q hi
    {
        const __nv_bfloat16* p = qhp + ((size_t)bh * SEQ + q0) * HEAD_D;
        #pragma unroll
        for (int i = 0; i < 4; i++) {
            int f = t + 256 * i;
            int row = f >> 3, chq = f & 7;
            cp16(sb + row * AP + chq * 16, p + row * HEAD_D + chq * 8);
        }
        CP_COMMIT();
    }
    load_k_tile(sb + SO_K0, khp, bh, 0, t);
    CP_COMMIT();
    CP_WAIT(1);
    __syncthreads();

    uint32_t qfh[4][4];
    #pragma unroll
    for (int ks = 0; ks < 4; ks++)
        ldsm4(qfh[ks], sb + (wid * 16 + aRow) * AP + ks * 32 + aCol);

    float m0 = -CUDART_INF_F, m1 = -CUDART_INF_F;   // per-row running max
    int r0g = q0 + wid * 16 + (lane >> 2);
    int rtop = q0 + wid * 16 + 15;                  // warp's last row
    const int nkt = qt * 2 + 2;

    // ---- 1a: scan, record row maxes + tile group maxes ----
    #pragma unroll 1
    for (int kt = 0; kt < nkt; kt++) {
        uint32_t cur = sb + ((kt & 1) ? SO_K1 : SO_K0);
        if (kt + 1 < nkt) {
            load_k_tile(sb + (((kt + 1) & 1) ? SO_K1 : SO_K0), khp, bh,
                        (kt + 1) * 64, t);
            CP_COMMIT();
            CP_WAIT(1);
        } else {
            CP_WAIT(0);
        }
        __syncthreads();

        float gm0 = -CUDART_INF_F, gm1 = -CUDART_INF_F;
        if (kt * 64 <= rtop) {           // warp-uniform: not fully masked
            float s[8][4];
            #pragma unroll
            for (int nb = 0; nb < 8; nb++)
                #pragma unroll
                for (int j = 0; j < 4; j++) s[nb][j] = 0.0f;
            #pragma unroll
            for (int ks = 0; ks < 4; ks++) {
                uint32_t bk[4][4];
                #pragma unroll
                for (int n4 = 0; n4 < 4; n4++)
                    ldsm4(bk[n4], cur + (n4 * 16 + bRow) * AP + ks * 32 + bCol);
                #pragma unroll
                for (int nb = 0; nb < 8; nb++)
                    mma16816(s[nb], qfh[ks], &bk[nb >> 1][(nb & 1) * 2]);
            }
            if (kt * 64 + 63 > q0 + wid * 16) {
                #pragma unroll
                for (int nb = 0; nb < 8; nb++) {
                    int gc = kt * 64 + nb * 8 + (lane & 3) * 2;
                    if (gc + 0 > r0g)     s[nb][0] = -CUDART_INF_F;
                    if (gc + 1 > r0g)     s[nb][1] = -CUDART_INF_F;
                    if (gc + 0 > r0g + 8) s[nb][2] = -CUDART_INF_F;
                    if (gc + 1 > r0g + 8) s[nb][3] = -CUDART_INF_F;
                }
            }
            float tm0 = -CUDART_INF_F, tm1 = -CUDART_INF_F;
            #pragma unroll
            for (int nb = 0; nb < 8; nb++) {
                tm0 = fmaxf(tm0, fmaxf(s[nb][0], s[nb][1]));
                tm1 = fmaxf(tm1, fmaxf(s[nb][2], s[nb][3]));
            }
            tm0 = fmaxf(tm0, __shfl_xor_sync(0xffffffffu, tm0, 1));
            tm0 = fmaxf(tm0, __shfl_xor_sync(0xffffffffu, tm0, 2));
            tm1 = fmaxf(tm1, __shfl_xor_sync(0xffffffffu, tm1, 1));
            tm1 = fmaxf(tm1, __shfl_xor_sync(0xffffffffu, tm1, 2));
            m0 = fmaxf(m0, tm0);
            m1 = fmaxf(m1, tm1);
            gm0 = tm0; gm1 = tm1;
            gm0 = fmaxf(gm0, __shfl_xor_sync(0xffffffffu, gm0, 4));
            gm0 = fmaxf(gm0, __shfl_xor_sync(0xffffffffu, gm0, 8));
            gm0 = fmaxf(gm0, __shfl_xor_sync(0xffffffffu, gm0, 16));
            gm1 = fmaxf(gm1, __shfl_xor_sync(0xffffffffu, gm1, 4));
            gm1 = fmaxf(gm1, __shfl_xor_sync(0xffffffffu, gm1, 8));
            gm1 = fmaxf(gm1, __shfl_xor_sync(0xffffffffu, gm1, 16));
        }
        if (lane == 0) {
            tmx[(wid * 32 + kt) * 2 + 0] = gm0;
            tmx[(wid * 32 + kt) * 2 + 1] = gm1;
        }
        __syncthreads();
    }

    // warp-min of row maxes (for tile pruning)
    float wmin = fminf(m0, m1);
    wmin = fminf(wmin, __shfl_xor_sync(0xffffffffu, wmin, 4));
    wmin = fminf(wmin, __shfl_xor_sync(0xffffffffu, wmin, 8));
    wmin = fminf(wmin, __shfl_xor_sync(0xffffffffu, wmin, 16));
    float thr = wmin - (CAND_MARGIN + 1.0f);

    // ---- 1b: revisit candidate tiles ----
    #pragma unroll 1
    for (int kt = 0; kt < nkt; kt++) {
        bool wact = (tmx[(wid * 32 + kt) * 2 + 0] >= thr) ||
                    (tmx[(wid * 32 + kt) * 2 + 1] >= thr);
        if (lane == 0) afl[(kt & 1) * 8 + wid] = wact ? 1 : 0;
        __syncthreads();
        int any = 0;
        #pragma unroll
        for (int w = 0; w < 8; w++) any |= afl[(kt & 1) * 8 + w];
        if (!any) continue;              // CTA-uniform skip

        load_k_tile(sb + SO_K0, khp, bh, kt * 64, t);
        CP_COMMIT();
        CP_WAIT(0);
        __syncthreads();

        if (wact && kt * 64 <= rtop) {
            float s[8][4];
            #pragma unroll
            for (int nb = 0; nb < 8; nb++)
                #pragma unroll
                for (int j = 0; j < 4; j++) s[nb][j] = 0.0f;
            #pragma unroll
            for (int ks = 0; ks < 4; ks++) {
                uint32_t bk[4][4];
                #pragma unroll
                for (int n4 = 0; n4 < 4; n4++)
                    ldsm4(bk[n4], sb + SO_K0 + (n4 * 16 + bRow) * AP + ks * 32 + bCol);
                #pragma unroll
                for (int nb = 0; nb < 8; nb++)
                    mma16816(s[nb], qfh[ks], &bk[nb >> 1][(nb & 1) * 2]);
            }
            if (kt * 64 + 63 > q0 + wid * 16) {
                #pragma unroll
                for (int nb = 0; nb < 8; nb++) {
                    int gc = kt * 64 + nb * 8 + (lane & 3) * 2;
                    if (gc + 0 > r0g)     s[nb][0] = -CUDART_INF_F;
                    if (gc + 1 > r0g)     s[nb][1] = -CUDART_INF_F;
                    if (gc + 0 > r0g + 8) s[nb][2] = -CUDART_INF_F;
                    if (gc + 1 > r0g + 8) s[nb][3] = -CUDART_INF_F;
                }
            }
            int grow0 = bh * SEQ + r0g;
            int grow1 = grow0 + 8;
            float th0 = m0 - CAND_MARGIN;
            float th1 = m1 - CAND_MARGIN;
            #pragma unroll
            for (int nb = 0; nb < 8; nb++) {
                int kbase = kt * 64 + nb * 8 + (lane & 3) * 2;
                if (s[nb][0] >= th0) {
                    int idx = atomicAdd(&g_cnt[grow0], 1);
                    if (idx < MAX_CAND) g_cand[grow0 * MAX_CAND + idx] = kbase;
                }
                if (s[nb][1] >= th0) {
                    int idx = atomicAdd(&g_cnt[grow0], 1);
                    if (idx < MAX_CAND) g_cand[grow0 * MAX_CAND + idx] = kbase + 1;
                }
                if (s[nb][2] >= th1) {
                    int idx = atomicAdd(&g_cnt[grow1], 1);
                    if (idx < MAX_CAND) g_cand[grow1 * MAX_CAND + idx] = kbase;
                }
                if (s[nb][3] >= th1) {
                    int idx = atomicAdd(&g_cnt[grow1], 1);
                    if (idx < MAX_CAND) g_cand[grow1 * MAX_CAND + idx] = kbase + 1;
                }
            }
        }
        __syncthreads();
    }
}

// ---------------------------------------------------------------------------
// Attention phase 2: exact fp32 softmax over candidates.
// ---------------------------------------------------------------------------
__global__ __launch_bounds__(256)
void attn_gather(const float* __restrict__ qkv,
                 __nv_bfloat16* __restrict__ ch,
                 __nv_bfloat16* __restrict__ cm)
{
    int w    = (blockIdx.x * 256 + threadIdx.x) >> 5;   // global row
    int lane = threadIdx.x & 31;
    int bh = w >> 11;            // / SEQ
    int sq = w & (SEQ - 1);
    int b  = bh >> 4;
    int h  = bh & 15;

    const float* qb = qkv + ((size_t)(b * SEQ + sq)) * QKV_N + h * HEAD_D;
    float q0 = qb[lane * 2]     * ATTN_SCALE;
    float q1 = qb[lane * 2 + 1] * ATTN_SCALE;

    int cnt = g_cnt[w];
    if (cnt > MAX_CAND) cnt = MAX_CAND;

    size_t off = (size_t)(b * SEQ + sq) * HIDDEN + h * HEAD_D + lane * 2;
    if (cnt <= 0) {              // defensive (argmax key always present)
        store_split2(ch, cm, off, 0.0f, 0.0f);
        return;
    }

    // load + sort candidate indices (determinism; insertion sort, n<=16)
    int cd[MAX_CAND];
    #pragma unroll
    for (int i = 0; i < MAX_CAND; i++)
        cd[i] = (i < cnt) ? g_cand[w * MAX_CAND + i] : 0x7fffffff;
    #pragma unroll
    for (int i = 1; i < MAX_CAND; i++) {
        int key = cd[i];
        #pragma unroll
        for (int j = i - 1; j >= 0; j--) {
            if (cd[j] > key) { cd[j + 1] = cd[j]; cd[j] = key; key = cd[j]; }
        }
    }

    // exact logits
    float sv[MAX_CAND];
    #pragma unroll
    for (int i = 0; i < MAX_CAND; i++) {
        float p = -CUDART_INF_F;
        if (i < cnt) {
            const float* kb = qkv + ((size_t)(b * SEQ + cd[i])) * QKV_N
                            + HIDDEN + h * HEAD_D;
            p = q0 * kb[lane * 2] + q1 * kb[lane * 2 + 1];
            p += __shfl_xor_sync(0xffffffffu, p, 16);
            p += __shfl_xor_sync(0xffffffffu, p, 8);
            p += __shfl_xor_sync(0xffffffffu, p, 4);
            p += __shfl_xor_sync(0xffffffffu, p, 2);
            p += __shfl_xor_sync(0xffffffffu, p, 1);
        }
        sv[i] = p;
    }

    float mx = -CUDART_INF_F;
    #pragma unroll
    for (int i = 0; i < MAX_CAND; i++) mx = fmaxf(mx, sv[i]);

    float l = 0.0f, o0 = 0.0f, o1 = 0.0f;
    #pragma unroll
    for (int i = 0; i < MAX_CAND; i++) {
        if (i < cnt) {
            float pe = __expf(sv[i] - mx);
            l += pe;
            const float* vb = qkv + ((size_t)(b * SEQ + cd[i])) * QKV_N
                            + 2 * HIDDEN + h * HEAD_D;
            o0 += pe * vb[lane * 2];
            o1 += pe * vb[lane * 2 + 1];
        }
    }
    float inv = 1.0f / l;
    store_split2(ch, cm, off, o0 * inv, o1 * inv);
}

// ---------------------------------------------------------------------------
extern "C" void kernel_launch(void* const* d_in, const int* in_sizes, int n_in,
                              void* d_out, int out_size)
{
    const float* x     = (const float*)d_in[0];
    const float* W_qkv = (const float*)d_in[1];
    const float* b_qkv = (const float*)d_in[2];
    const float* W_out = (const float*)d_in[3];
    const float* b_out = (const float*)d_in[4];
    float* out = (float*)d_out;

    float *qkv;
    __nv_bfloat16 *x_hi, *x_mid, *c_hi, *c_mid, *wq_hi, *wq_mid, *wo_hi, *wo_mid;
    __nv_bfloat16 *aqh, *akh;
    int* cnt_ptr;
    cudaGetSymbolAddress((void**)&qkv,    g_qkv);
    cudaGetSymbolAddress((void**)&x_hi,   g_x_hi);
    cudaGetSymbolAddress((void**)&x_mid,  g_x_mid);
    cudaGetSymbolAddress((void**)&c_hi,   g_c_hi);
    cudaGetSymbolAddress((void**)&c_mid,  g_c_mid);
    cudaGetSymbolAddress((void**)&wq_hi,  g_wq_hi);
    cudaGetSymbolAddress((void**)&wq_mid, g_wq_mid);
    cudaGetSymbolAddress((void**)&wo_hi,  g_wo_hi);
    cudaGetSymbolAddress((void**)&wo_mid, g_wo_mid);
    cudaGetSymbolAddress((void**)&aqh,    g_aq_hi);
    cudaGetSymbolAddress((void**)&akh,    g_ak_hi);
    cudaGetSymbolAddress((void**)&cnt_ptr, g_cnt);

    cudaFuncSetAttribute(mma_gemm, cudaFuncAttributeMaxDynamicSharedMemorySize,
                         SMEM_MMA);
    cudaFuncSetAttribute(attn_scan, cudaFuncAttributeMaxDynamicSharedMemorySize,
                         SMEM_SCAN);

    // 0) zero candidate counters
    zero_cnt<<<(NROWS + 255) / 256, 256>>>(cnt_ptr);
    // 1) split x -> bf16 hi/mid
    {
        int n4 = M_TOT * HIDDEN / 4;
        split_rows<<<(n4 + 255) / 256, 256>>>((const float4*)x,
                                              (__nv_bfloat162*)x_hi,
                                              (__nv_bfloat162*)x_mid, n4);
    }
    // 2) transpose+split W_qkv
    split_transpose<<<dim3(QKV_N / 32, KDIM / 32), dim3(32, 8)>>>(
        W_qkv, wq_hi, wq_mid, KDIM, QKV_N);
    // 3) QKV projection (tensor cores, 2 CTAs/SM)
    mma_gemm<<<dim3(QKV_N / GBN, M_TOT / GBM), 256, SMEM_MMA>>>(
        x_hi, x_mid, wq_hi, wq_mid, b_qkv, qkv, QKV_N);
    // 4) prep bf16-hi Q/K
    attn_prep2<<<dim3(SEQ / 64, HEADS, BATCH), 256>>>(qkv, aqh, akh);
    // 5) phase 1: scan + candidate extraction
    attn_scan<<<dim3(SEQ / 128, HEADS, BATCH), 256, SMEM_SCAN>>>(aqh, akh);
    // 6) phase 2: exact softmax over candidates -> ctx hi/mid
    attn_gather<<<NROWS / 8, 256>>>(qkv, c_hi, c_mid);
    // 7) transpose+split W_out
    split_transpose<<<dim3(HIDDEN / 32, KDIM / 32), dim3(32, 8)>>>(
        W_out, wo_hi, wo_mid, KDIM, HIDDEN);
    // 8) output projection (tensor cores, 2 CTAs/SM)
    mma_gemm<<<dim3(HIDDEN / GBN, M_TOT / GBM), 256, SMEM_MMA>>>(
        c_hi, c_mid, wo_hi, wo_mid, b_out, out, HIDDEN);
}